// round 13
// baseline (speedup 1.0000x reference)
#include <cuda_runtime.h>
#include <cuda_bf16.h>
#include <cuda_fp16.h>
#include <math.h>
#include <stdint.h>

// ---------------- problem constants ----------------
#define B_    256
#define L_    197
#define LP    196
#define D_    768
#define HD    512
#define DH    128
#define NH    4
#define NC    1000
#define FLATN 2883   // 3*31*31
#define FPAD  2944   // flat padded to multiple of 32
#define NPAD  1024   // classifier N padded
#define HK_CLS_CHUNKS  24          // 768/32
#define HK_CHUNKS      116         // 24 + 92
#define HK_SPLIT       29          // chunks per k-split (116/4)

// ---------------- scratch (static __device__, no allocation) ----------------
__device__ __half g_xph[(size_t)B_ * LP * HD];        // 50176 x 512 (fp16)
__device__ float g_cov[(size_t)B_ * 3 * DH * DH];     // (b,p,d,e) NCHW

// fp16 buffers for tensor-core projection GEMM (single-pass: hi only)
__device__ __half gA_h[(size_t)B_ * LP * D_];    // [50176,768]
__device__ __half gWt_h[(size_t)HD * D_];        // [512,768]  W^T

// LN output (UNcentered) fp16 hi, natural layout (h,b, l=196, d=128)
__device__ __half gHn_h[(size_t)NH * B_ * LP * DH];
__device__ float gSh[(size_t)NH * B_ * DH];   // sum_l hi(hn)  (per column)
__device__ float gM [(size_t)NH * B_];        // tile mean (exact)

// classifier-head fp16 buffers (3-pass: hi+lo kept for accuracy)
__device__ __half gW1_h[(size_t)D_ * NPAD];      // [768,1024]
__device__ __half gW1_l[(size_t)D_ * NPAD];
__device__ __half gW2_h[(size_t)FPAD * NPAD];    // [2944,1024]
__device__ __half gW2_l[(size_t)FPAD * NPAD];
__device__ __half gCls_h[(size_t)B_ * D_];       // [256,768]
__device__ __half gCls_l[(size_t)B_ * D_];
__device__ __half gF_h[(size_t)B_ * FPAD];       // [256,2944]
__device__ __half gF_l[(size_t)B_ * FPAD];

// ---------------- baseline-PTX helpers ----------------
__device__ __forceinline__ uint32_t smem_u32(const void* p) {
    uint32_t a;
    asm("{ .reg .u64 t; cvta.to.shared.u64 t, %1; cvt.u32.u64 %0, t; }"
        : "=r"(a) : "l"(p));
    return a;
}
__device__ __forceinline__ void cp16(uint32_t dst, const void* src) {
    asm volatile("cp.async.ca.shared.global [%0], [%1], 16;"
                 :: "r"(dst), "l"(src) : "memory");
}
#define CP_COMMIT() asm volatile("cp.async.commit_group;" ::: "memory")
#define CP_WAIT0()  asm volatile("cp.async.wait_group 0;" ::: "memory")
#define CP_WAIT1()  asm volatile("cp.async.wait_group 1;" ::: "memory")

__device__ __forceinline__ void ldx4(uint32_t* r, uint32_t addr) {
    asm volatile("ldmatrix.sync.aligned.m8n8.x4.shared.b16 {%0,%1,%2,%3}, [%4];"
                 : "=r"(r[0]), "=r"(r[1]), "=r"(r[2]), "=r"(r[3]) : "r"(addr));
}
__device__ __forceinline__ void ldx4t(uint32_t* r, uint32_t addr) {
    asm volatile("ldmatrix.sync.aligned.m8n8.x4.trans.shared.b16 {%0,%1,%2,%3}, [%4];"
                 : "=r"(r[0]), "=r"(r[1]), "=r"(r[2]), "=r"(r[3]) : "r"(addr));
}
__device__ __forceinline__ void mma16816(float* c, const uint32_t* a,
                                         uint32_t b0, uint32_t b1) {
    asm volatile(
        "mma.sync.aligned.m16n8k16.row.col.f32.f16.f16.f32 "
        "{%0,%1,%2,%3}, {%4,%5,%6,%7}, {%8,%9}, {%0,%1,%2,%3};"
        : "+f"(c[0]), "+f"(c[1]), "+f"(c[2]), "+f"(c[3])
        : "r"(a[0]), "r"(a[1]), "r"(a[2]), "r"(a[3]), "r"(b0), "r"(b1));
}

// =====================================================================
// K0a: round x[:,1:,:] to fp16  [50176,768]
// =====================================================================
__global__ void __launch_bounds__(256) k_convA(const float* __restrict__ X)
{
    const int total = B_ * LP * (D_ / 4);
    for (int i = blockIdx.x * blockDim.x + threadIdx.x; i < total;
         i += gridDim.x * blockDim.x) {
        const int m  = i / (D_ / 4);
        const int k4 = i - m * (D_ / 4);
        const int b  = m / LP;
        const int l  = m - b * LP + 1;
        float4 v = *(const float4*)(X + ((size_t)(b * L_ + l)) * D_ + k4 * 4);
        __half2 h01, h23;
        h01.x = __float2half_rn(v.x); h01.y = __float2half_rn(v.y);
        h23.x = __float2half_rn(v.z); h23.y = __float2half_rn(v.w);
        ((__half2*)gA_h)[(size_t)i * 2]     = h01;
        ((__half2*)gA_h)[(size_t)i * 2 + 1] = h23;
    }
}

// =====================================================================
// K0b: W [768,512] -> W^T fp16 [512,768] (hi only; single-pass GEMM)
// =====================================================================
__global__ void __launch_bounds__(256) k_convW(const float* __restrict__ W)
{
    __shared__ float t[32][33];
    const int nb = blockIdx.x * 32;
    const int kb = blockIdx.y * 32;
    const int tx = threadIdx.x & 31, ty = threadIdx.x >> 5;
#pragma unroll
    for (int r = 0; r < 32; r += 8)
        t[ty + r][tx] = W[(size_t)(kb + ty + r) * HD + nb + tx];
    __syncthreads();
#pragma unroll
    for (int r = 0; r < 32; r += 8)
        gWt_h[(size_t)(nb + ty + r) * D_ + kb + tx] = __float2half_rn(t[tx][ty + r]);
}

// =====================================================================
// K0c: head-weight conversions + out init
// =====================================================================
#define CH_S1 (D_ * NPAD)
#define CH_S2 ((size_t)FPAD * NPAD)
#define CH_S3 (B_ * D_)
#define CH_S4 (B_ * NC)
#define CH_TOTAL (CH_S1 + CH_S2 + CH_S3 + CH_S4)

__global__ void __launch_bounds__(256) k_convH(
    const float* __restrict__ w1, const float* __restrict__ w2,
    const float* __restrict__ cls, const float* __restrict__ b1,
    const float* __restrict__ b2, float* __restrict__ out)
{
    for (size_t i = (size_t)blockIdx.x * 256 + threadIdx.x; i < CH_TOTAL;
         i += (size_t)gridDim.x * 256) {
        if (i < CH_S1) {
            const int r = (int)(i >> 10), c = (int)(i & 1023);
            float v = (c < NC) ? w1[(size_t)r * NC + c] : 0.f;
            const __half h = __float2half_rn(v);
            gW1_h[i] = h;
            gW1_l[i] = __float2half_rn(v - __half2float(h));
        } else if (i < CH_S1 + CH_S2) {
            const size_t j = i - CH_S1;
            const int r = (int)(j >> 10), c = (int)(j & 1023);
            float v = (r < FLATN && c < NC) ? w2[(size_t)r * NC + c] : 0.f;
            const __half h = __float2half_rn(v);
            gW2_h[j] = h;
            gW2_l[j] = __float2half_rn(v - __half2float(h));
        } else if (i < CH_S1 + CH_S2 + CH_S3) {
            const size_t j = i - CH_S1 - CH_S2;
            float v = cls[j];
            const __half h = __float2half_rn(v);
            gCls_h[j] = h;
            gCls_l[j] = __float2half_rn(v - __half2float(h));
        } else {
            const size_t j = i - CH_S1 - CH_S2 - CH_S3;
            const int n = (int)(j % NC);
            out[j] = 0.5f * (b1[n] + b2[n]);
        }
    }
}

// =====================================================================
// K1: warp-mma fp16 single-pass GEMM: xp = A_h @ B_h    <- ncu probe
// CTA tile 128x256 (grid 392x2), BK=32, 8 warps, warp tile 64x64.
// A DRAM re-reads 4x -> 2x; fp16 epilogue halves the xp write.
// =====================================================================
#define RSB      80
#define GOFF_A   0
#define GOFF_B   (128 * RSB)            // 10240
#define GSTAGE   (384 * RSB)            // 30720 (A 128 rows + B 256 rows)
#define GEMM_SMEM (2 * GSTAGE)          // 61440
#define NCHUNK   (D_ / 32)              // 24

__device__ __forceinline__ void gemm_load_stage(
    uint32_t sb, int buf, int c, int m0, int n0, int tid)
{
    const int k0 = c * 32;
    const uint32_t stg = sb + buf * GSTAGE;
#pragma unroll
    for (int q = 0; q < 6; q++) {
        const int ch = q * 256 + tid;       // 0..1535 (16B units)
        if (ch < 512) {                     // A: 128 rows x 4 units
            const int row = ch >> 2;
            const int cc  = ch & 3;
            cp16(stg + GOFF_A + (uint32_t)row * RSB + cc * 16,
                 gA_h + (size_t)(m0 + row) * D_ + k0 + cc * 8);
        } else {                            // B: 256 rows x 4 units
            const int u   = ch - 512;
            const int row = u >> 2;
            const int cc  = u & 3;
            cp16(stg + GOFF_B + (uint32_t)row * RSB + cc * 16,
                 gWt_h + (size_t)(n0 + row) * D_ + k0 + cc * 8);
        }
    }
}

__global__ void __launch_bounds__(256) k_gemm_mma(const float* __restrict__ bias)
{
    extern __shared__ char smem[];
    const uint32_t sb = smem_u32(smem);
    const int tid  = threadIdx.x;
    const int wid  = tid >> 5;
    const int lane = tid & 31;
    const int wm = wid >> 2;              // 0..1 (m 64 each)
    const int wn = wid & 3;               // 0..3 (n 64 each -> 256)
    const int m0 = blockIdx.x * 128;
    const int n0 = blockIdx.y * 256;

    const uint32_t a_row = (lane & 15);
    const uint32_t a_col = (uint32_t)(lane >> 4) * 16;
    const uint32_t b_row = (lane & 7) + ((lane >> 4) << 3);
    const uint32_t b_col = (uint32_t)((lane >> 3) & 1) * 16;

    uint32_t a_off[4], b_off[4];
#pragma unroll
    for (int mt = 0; mt < 4; mt++)
        a_off[mt] = GOFF_A + (uint32_t)(wm * 64 + mt * 16 + a_row) * RSB + a_col;
#pragma unroll
    for (int g = 0; g < 4; g++)
        b_off[g] = GOFF_B + (uint32_t)(wn * 64 + g * 16 + b_row) * RSB + b_col;

    float acc[4][8][4];
#pragma unroll
    for (int mt = 0; mt < 4; mt++)
#pragma unroll
        for (int nt = 0; nt < 8; nt++)
#pragma unroll
            for (int e = 0; e < 4; e++) acc[mt][nt][e] = 0.f;

    gemm_load_stage(sb, 0, 0, m0, n0, tid);
    CP_COMMIT();

    for (int c = 0; c < NCHUNK; c++) {
        if (c + 1 < NCHUNK) {
            gemm_load_stage(sb, (c + 1) & 1, c + 1, m0, n0, tid);
            CP_COMMIT();
            CP_WAIT1();
        } else {
            CP_WAIT0();
        }
        __syncthreads();

        const uint32_t stg = sb + (c & 1) * GSTAGE;
#pragma unroll
        for (int ks = 0; ks < 2; ks++) {
            const uint32_t kb = (uint32_t)ks * 32;
            uint32_t ah[4][4];
#pragma unroll
            for (int mt = 0; mt < 4; mt++)
                ldx4(ah[mt], stg + a_off[mt] + kb);
#pragma unroll
            for (int g = 0; g < 4; g++) {
                uint32_t bh[4];
                ldx4(bh, stg + b_off[g] + kb);
#pragma unroll
                for (int mt = 0; mt < 4; mt++)
                    mma16816(acc[mt][2 * g],     ah[mt], bh[0], bh[1]);
#pragma unroll
                for (int mt = 0; mt < 4; mt++)
                    mma16816(acc[mt][2 * g + 1], ah[mt], bh[2], bh[3]);
            }
        }
        __syncthreads();
    }

    const int gid = lane >> 2;
    const int tig = lane & 3;
#pragma unroll
    for (int mt = 0; mt < 4; mt++) {
        const int r0 = m0 + wm * 64 + mt * 16 + gid;
#pragma unroll
        for (int nt = 0; nt < 8; nt++) {
            const int col = n0 + wn * 64 + nt * 8 + 2 * tig;
            const float b0 = bias[col], b1v = bias[col + 1];
            __half2 v0, v1;
            v0.x = __float2half_rn(acc[mt][nt][0] + b0);
            v0.y = __float2half_rn(acc[mt][nt][1] + b1v);
            v1.x = __float2half_rn(acc[mt][nt][2] + b0);
            v1.y = __float2half_rn(acc[mt][nt][3] + b1v);
            *(__half2*)(g_xph + (size_t)r0 * HD + col)       = v0;
            *(__half2*)(g_xph + (size_t)(r0 + 8) * HD + col) = v1;
        }
    }
}

// =====================================================================
// K2: streaming LayerNorm (reads fp16 xp) -> fp16 hi + column sums +
// exact tile mean (centering folded into cov as rank-1 correction)
// =====================================================================
__global__ void __launch_bounds__(256) k_lnc(
    const float* __restrict__ g, const float* __restrict__ be)
{
    __shared__ float smh[8][128];
    __shared__ float smf[8][128];

    const int h = blockIdx.x >> 8;
    const int b = blockIdx.x & 255;
    const int tid  = threadIdx.x;
    const int warp = tid >> 5;
    const int lane = tid & 31;

    const float4 gv = *(const float4*)(g + lane * 4);
    const float4 bv = *(const float4*)(be + lane * 4);

    __half* dst_h = gHn_h + ((size_t)(h * B_ + b)) * LP * DH;

    float sh0 = 0.f, sh1 = 0.f, sh2 = 0.f, sh3 = 0.f;
    float sf0 = 0.f, sf1 = 0.f, sf2 = 0.f, sf3 = 0.f;

    for (int l = warp; l < LP; l += 8) {
        const __half* src = g_xph + ((size_t)(b * LP + l)) * HD + h * DH;
        const uint2 u = *(const uint2*)(src + lane * 4);
        const __half2 p01 = *(const __half2*)&u.x;
        const __half2 p23 = *(const __half2*)&u.y;
        const float x0 = __half2float(p01.x), x1 = __half2float(p01.y);
        const float x2 = __half2float(p23.x), x3 = __half2float(p23.y);

        float s = x0 + x1 + x2 + x3;
#pragma unroll
        for (int o = 16; o; o >>= 1) s += __shfl_xor_sync(0xffffffffu, s, o);
        const float mu = s * (1.0f / 128.0f);

        const float d0 = x0 - mu, d1 = x1 - mu, d2 = x2 - mu, d3 = x3 - mu;
        float sq = d0 * d0 + d1 * d1 + d2 * d2 + d3 * d3;
#pragma unroll
        for (int o = 16; o; o >>= 1) sq += __shfl_xor_sync(0xffffffffu, sq, o);
        const float rstd = rsqrtf(sq * (1.0f / 128.0f) + 1e-5f);

        const float o0 = d0 * rstd * gv.x + bv.x;
        const float o1 = d1 * rstd * gv.y + bv.y;
        const float o2 = d2 * rstd * gv.z + bv.z;
        const float o3 = d3 * rstd * gv.w + bv.w;

        const __half h0 = __float2half_rn(o0);
        const __half h1 = __float2half_rn(o1);
        const __half h2 = __float2half_rn(o2);
        const __half h3 = __float2half_rn(o3);
        __half2 hh01; hh01.x = h0; hh01.y = h1;
        __half2 hh23; hh23.x = h2; hh23.y = h3;

        const size_t ro = (size_t)l * DH + lane * 4;
        *(__half2*)(dst_h + ro)     = hh01;
        *(__half2*)(dst_h + ro + 2) = hh23;

        sh0 += __half2float(h0); sh1 += __half2float(h1);
        sh2 += __half2float(h2); sh3 += __half2float(h3);
        sf0 += o0; sf1 += o1; sf2 += o2; sf3 += o3;
    }
    smh[warp][lane * 4 + 0] = sh0; smh[warp][lane * 4 + 1] = sh1;
    smh[warp][lane * 4 + 2] = sh2; smh[warp][lane * 4 + 3] = sh3;
    smf[warp][lane * 4 + 0] = sf0; smf[warp][lane * 4 + 1] = sf1;
    smf[warp][lane * 4 + 2] = sf2; smf[warp][lane * 4 + 3] = sf3;
    __syncthreads();

    if (tid < 128) {
        float th = 0.f, tf = 0.f;
#pragma unroll
        for (int w = 0; w < 8; w++) { th += smh[w][tid]; tf += smf[w][tid]; }
        gSh[(size_t)(h * B_ + b) * DH + tid] = th;
        smf[0][tid] = tf;
    }
    __syncthreads();
    if (tid < 32) {
        float t = smf[0][tid] + smf[0][tid + 32] + smf[0][tid + 64] + smf[0][tid + 96];
#pragma unroll
        for (int o = 16; o; o >>= 1) t += __shfl_xor_sync(0xffffffffu, t, o);
        if (tid == 0) gM[h * B_ + b] = t * (1.0f / (LP * DH));
    }
}

// =====================================================================
// K3: cov via fp16 mma single-pass, trans-ldmatrix, rank-1 centering
// =====================================================================
#define CRS2   136
#define CRSB2  (CRS2 * 2)               // 272 B
#define CTILE2 (208 * CRSB2)            // 56576
#define COV_SMEM (2 * CTILE2)           // 113,152

__global__ void __launch_bounds__(256) k_cov_mma()
{
    extern __shared__ char csm[];
    const uint32_t sb = smem_u32(csm);
    __shared__ float colsq[DH];
    __shared__ float s1s[DH];
    __shared__ float s2s[DH];

    const int p = blockIdx.x;
    const int b = blockIdx.y;
    const int tid  = threadIdx.x;
    const int wid  = tid >> 5;
    const int lane = tid & 31;
    const int wm = wid >> 1;
    const int wn = wid & 1;

    const __half* Asrc = gHn_h + ((size_t)(p * B_ + b)) * LP * DH;
    const __half* Bhs  = gHn_h + ((size_t)((p + 1) * B_ + b)) * LP * DH;

    const uint32_t tA = sb, tBh = sb + CTILE2;

    for (int i = tid; i < 2 * 12 * 17; i += 256) {
        const int tile = i / 204;
        const int rem  = i % 204;
        const int r    = rem / 17;
        const int c    = rem % 17;
        *(uint4*)(csm + (size_t)tile * CTILE2 + (196 + r) * CRSB2 + c * 16) =
            make_uint4(0u, 0u, 0u, 0u);
    }
    for (int t = tid; t < LP * 16; t += 256) {
        const int row = t >> 4;
        const int ch  = t & 15;
        const uint32_t doff = (uint32_t)row * CRSB2 + ch * 16;
        const size_t   goff = (size_t)row * DH + ch * 8;
        cp16(tA  + doff, Asrc + goff);
        cp16(tBh + doff, Bhs + goff);
    }
    CP_COMMIT();
    if (tid < DH) {
        colsq[tid] = 0.f;
        s1s[tid] = gSh[(size_t)(p * B_ + b) * DH + tid];
        s2s[tid] = gSh[(size_t)((p + 1) * B_ + b) * DH + tid];
    }
    CP_WAIT0();
    __syncthreads();

    const uint32_t ar = (lane & 7) + ((lane >> 4) << 3);
    const uint32_t ac = ((lane >> 3) & 1) * 16;
    const uint32_t br = (lane & 7) + (((lane >> 3) & 1) << 3);
    const uint32_t bc = (uint32_t)(lane >> 4) * 16;

    uint32_t a_off[2], b_off[4];
#pragma unroll
    for (int mt = 0; mt < 2; mt++)
        a_off[mt] = ar * CRSB2 + (uint32_t)(wm * 32 + mt * 16) * 2 + ac;
#pragma unroll
    for (int g = 0; g < 4; g++)
        b_off[g] = br * CRSB2 + (uint32_t)(wn * 64 + g * 16) * 2 + bc;

    float acc[2][8][4];
#pragma unroll
    for (int mt = 0; mt < 2; mt++)
#pragma unroll
        for (int nt = 0; nt < 8; nt++)
#pragma unroll
            for (int e = 0; e < 4; e++) acc[mt][nt][e] = 0.f;

#pragma unroll
    for (int ks = 0; ks < 13; ks++) {
        const uint32_t kb = (uint32_t)ks * 16 * CRSB2;
        uint32_t ah[2][4];
#pragma unroll
        for (int mt = 0; mt < 2; mt++)
            ldx4t(ah[mt], tA + a_off[mt] + kb);
#pragma unroll
        for (int g = 0; g < 4; g++) {
            uint32_t bh[4];
            ldx4t(bh, tBh + b_off[g] + kb);
#pragma unroll
            for (int mt = 0; mt < 2; mt++) {
                mma16816(acc[mt][2 * g],     ah[mt], bh[0], bh[1]);
                mma16816(acc[mt][2 * g + 1], ah[mt], bh[2], bh[3]);
            }
        }
    }

    const float m1 = gM[p * B_ + b];
    const float m2 = gM[(p + 1) * B_ + b];
    const float c12 = (float)LP * m1 * m2;
    const int gid = lane >> 2;
    const int tig = lane & 3;
#pragma unroll
    for (int mt = 0; mt < 2; mt++) {
        const int d0 = wm * 32 + mt * 16 + gid;
        const float t1a = m2 * s1s[d0]     - c12;
        const float t1b = m2 * s1s[d0 + 8] - c12;
#pragma unroll
        for (int nt = 0; nt < 8; nt++) {
            const int e0 = wn * 64 + nt * 8 + 2 * tig;
            const float t2a = m1 * s2s[e0];
            const float t2b = m1 * s2s[e0 + 1];
            acc[mt][nt][0] -= t1a + t2a;
            acc[mt][nt][1] -= t1a + t2b;
            acc[mt][nt][2] -= t1b + t2a;
            acc[mt][nt][3] -= t1b + t2b;
        }
    }

#pragma unroll
    for (int nt = 0; nt < 8; nt++) {
        float s0 = acc[0][nt][0] * acc[0][nt][0] + acc[0][nt][2] * acc[0][nt][2]
                 + acc[1][nt][0] * acc[1][nt][0] + acc[1][nt][2] * acc[1][nt][2];
        float s1 = acc[0][nt][1] * acc[0][nt][1] + acc[0][nt][3] * acc[0][nt][3]
                 + acc[1][nt][1] * acc[1][nt][1] + acc[1][nt][3] * acc[1][nt][3];
#pragma unroll
        for (int o = 4; o <= 16; o <<= 1) {
            s0 += __shfl_xor_sync(0xffffffffu, s0, o);
            s1 += __shfl_xor_sync(0xffffffffu, s1, o);
        }
        if (lane < 4) {
            const int col = wn * 64 + nt * 8 + 2 * lane;
            atomicAdd(&colsq[col], s0);
            atomicAdd(&colsq[col + 1], s1);
        }
    }
    __syncthreads();

    float* outb = g_cov + ((size_t)(b * 3 + p)) * (DH * DH);
#pragma unroll
    for (int nt = 0; nt < 8; nt++) {
        const int col = wn * 64 + nt * 8 + 2 * tig;
        const float i0 = 1.0f / fmaxf(sqrtf(colsq[col]),     (float)LP * 1e-12f);
        const float i1 = 1.0f / fmaxf(sqrtf(colsq[col + 1]), (float)LP * 1e-12f);
#pragma unroll
        for (int mt = 0; mt < 2; mt++) {
            const int r0 = wm * 32 + mt * 16 + gid;
            float2 v0 = make_float2(acc[mt][nt][0] * i0, acc[mt][nt][1] * i1);
            float2 v1 = make_float2(acc[mt][nt][2] * i0, acc[mt][nt][3] * i1);
            *(float2*)(outb + (size_t)r0 * DH + col)       = v0;
            *(float2*)(outb + (size_t)(r0 + 8) * DH + col) = v1;
        }
    }
}

// =====================================================================
// K4: fused conv1 -> GELU -> conv2 ; emits flat as fp16 hi/lo (padded)
// =====================================================================
#define CONV_CS_B  (3 * 66 * 128 * 4)
#define CONV_SMEM  (CONV_CS_B + 3 * 3969 * 4)  // 149,004

__global__ void __launch_bounds__(256) k_conv(
    const float* __restrict__ w1, const float* __restrict__ w2)
{
    extern __shared__ char cvsm[];
    float* cs = (float*)cvsm;
    float* z1 = (float*)(cvsm + CONV_CS_B);
    __shared__ float w1s[81];
    __shared__ float w2s[81];

    const int b = blockIdx.x;
    const int tid = threadIdx.x;
    if (tid < 81) { w1s[tid] = w1[tid]; w2s[tid] = w2[tid]; }

    const float* cb = g_cov + (size_t)b * 3 * DH * DH;

#pragma unroll 1
    for (int ph = 0; ph < 2; ph++) {
        const int r0 = ph * 64;
        const int nr = ph ? 64 : 66;
        const int y0 = ph ? 32 : 0;
        const int ny = ph ? 31 : 32;
        __syncthreads();
        for (int i = tid; i < 3 * nr * 32; i += 256) {
            const int c  = i / (nr * 32);
            const int rr = (i / 32) % nr;
            const int q  = i % 32;
            *(float4*)(cs + (c * 66 + rr) * 128 + q * 4) =
                *(const float4*)(cb + (size_t)c * (DH * DH) + (r0 + rr) * DH + q * 4);
        }
        __syncthreads();
        for (int idx = tid; idx < 3 * ny * 63; idx += 256) {
            const int c = idx / (ny * 63);
            const int r = idx % (ny * 63);
            const int y = y0 + r / 63;
            const int x = r % 63;
            float s = 0.f;
#pragma unroll
            for (int ci = 0; ci < 3; ci++)
#pragma unroll
                for (int ky = 0; ky < 3; ky++)
#pragma unroll
                    for (int kx = 0; kx < 3; kx++)
                        s += cs[(ci * 66 + (2 * y + ky - r0)) * 128 + 2 * x + kx]
                           * w1s[((c * 3 + ci) * 3 + ky) * 3 + kx];
            s = 0.5f * s * (1.0f + erff(s * 0.70710678118654752f));
            z1[c * 3969 + y * 63 + x] = s;
        }
    }
    __syncthreads();

    __half* fh = gF_h + (size_t)b * FPAD;
    __half* fl = gF_l + (size_t)b * FPAD;
    for (int idx = tid; idx < FLATN; idx += 256) {
        const int c = idx / 961;
        const int r = idx % 961;
        const int y = r / 31, x = r % 31;
        float s = 0.f;
#pragma unroll
        for (int ci = 0; ci < 3; ci++)
#pragma unroll
            for (int ky = 0; ky < 3; ky++)
#pragma unroll
                for (int kx = 0; kx < 3; kx++)
                    s += z1[ci * 3969 + (2 * y + ky) * 63 + (2 * x + kx)]
                       * w2s[((c * 3 + ci) * 3 + ky) * 3 + kx];
        const __half hv = __float2half_rn(s);
        fh[idx] = hv;
        fl[idx] = __float2half_rn(s - __half2float(hv));
    }
    for (int idx = FLATN + tid; idx < FPAD; idx += 256) {
        fh[idx] = __float2half_rn(0.f);
        fl[idx] = __float2half_rn(0.f);
    }
}

// =====================================================================
// K5: classifier head via fp16 mma, 3-pass split, k-split=4 + atomicAdd
// =====================================================================
#define HRSB   80
#define HBRS   272
#define OFF_AH2 0
#define OFF_AL2 (64 * HRSB)
#define OFF_BH2 (2 * 64 * HRSB)
#define OFF_BL2 (OFF_BH2 + 32 * HBRS)
#define HSTAGE  (OFF_BL2 + 32 * HBRS)   // 27648
#define HEAD_SMEM (2 * HSTAGE)          // 55296

__device__ __forceinline__ void head_load_stage(
    uint32_t sb, int buf, int chunk, int m0, int n0, int tid)
{
    const uint32_t stg = sb + buf * HSTAGE;
    const bool in_cls = (chunk < HK_CLS_CHUNKS);
    const int  kr     = in_cls ? chunk * 32 : (chunk - HK_CLS_CHUNKS) * 32;
    const __half* Ah = in_cls ? gCls_h : gF_h;
    const __half* Al = in_cls ? gCls_l : gF_l;
    const __half* Bh = in_cls ? gW1_h  : gW2_h;
    const __half* Bl = in_cls ? gW1_l  : gW2_l;
    const int astr = in_cls ? D_ : FPAD;

    {
        const int idx = tid;
        const int row = idx >> 2;
        const int q   = idx & 3;
        const uint32_t doff = (uint32_t)row * HRSB + q * 16;
        const size_t goff = (size_t)(m0 + row) * astr + kr + q * 8;
        cp16(stg + OFF_AH2 + doff, Ah + goff);
        cp16(stg + OFF_AL2 + doff, Al + goff);
    }
#pragma unroll
    for (int j = 0; j < 2; j++) {
        const int idx = j * 256 + tid;
        const int row = idx >> 4;
        const int q   = idx & 15;
        const uint32_t doff = (uint32_t)row * HBRS + q * 16;
        const size_t goff = (size_t)(kr + row) * NPAD + n0 + q * 8;
        cp16(stg + OFF_BH2 + doff, Bh + goff);
        cp16(stg + OFF_BL2 + doff, Bl + goff);
    }
}

__global__ void __launch_bounds__(256) k_head_mma(float* __restrict__ out)
{
    extern __shared__ char hsm[];
    const uint32_t sb = smem_u32(hsm);
    const int tid  = threadIdx.x;
    const int wid  = tid >> 5;
    const int lane = tid & 31;
    const int wm = wid >> 2;
    const int wn = wid & 3;
    const int m0 = blockIdx.x * 64;
    const int n0 = blockIdx.y * 128;
    const int c0 = blockIdx.z * HK_SPLIT;

    const uint32_t a_row = (lane & 15);
    const uint32_t a_col = (uint32_t)(lane >> 4) * 16;
    const uint32_t br = (lane & 7) + (((lane >> 3) & 1) << 3);
    const uint32_t bc = (uint32_t)(lane >> 4) * 16;

    uint32_t a_off[2], b_off[2];
#pragma unroll
    for (int mt = 0; mt < 2; mt++)
        a_off[mt] = (uint32_t)(wm * 32 + mt * 16 + a_row) * HRSB + a_col;
#pragma unroll
    for (int g = 0; g < 2; g++)
        b_off[g] = br * HBRS + (uint32_t)(wn * 32 + g * 16) * 2 + bc;

    float acc[2][4][4];
#pragma unroll
    for (int mt = 0; mt < 2; mt++)
#pragma unroll
        for (int nf = 0; nf < 4; nf++)
#pragma unroll
            for (int e = 0; e < 4; e++) acc[mt][nf][e] = 0.f;

    head_load_stage(sb, 0, c0, m0, n0, tid);
    CP_COMMIT();

    for (int i = 0; i < HK_SPLIT; i++) {
        if (i + 1 < HK_SPLIT) {
            head_load_stage(sb, (i + 1) & 1, c0 + i + 1, m0, n0, tid);
            CP_COMMIT();
            CP_WAIT1();
        } else {
            CP_WAIT0();
        }
        __syncthreads();

        const uint32_t stg = sb + (i & 1) * HSTAGE;
#pragma unroll
        for (int ks = 0; ks < 2; ks++) {
            uint32_t ah[2][4], al[2][4];
#pragma unroll
            for (int mt = 0; mt < 2; mt++) {
                ldx4(ah[mt], stg + OFF_AH2 + a_off[mt] + ks * 32);
                ldx4(al[mt], stg + OFF_AL2 + a_off[mt] + ks * 32);
            }
            const uint32_t kbb = (uint32_t)ks * 16 * HBRS;
#pragma unroll
            for (int g = 0; g < 2; g++) {
                uint32_t bh[4], bl[4];
                ldx4t(bh, stg + OFF_BH2 + b_off[g] + kbb);
                ldx4t(bl, stg + OFF_BL2 + b_off[g] + kbb);
#pragma unroll
                for (int mt = 0; mt < 2; mt++) {
                    mma16816(acc[mt][2 * g],     ah[mt], bh[0], bh[1]);
                    mma16816(acc[mt][2 * g],     ah[mt], bl[0], bl[1]);
                    mma16816(acc[mt][2 * g],     al[mt], bh[0], bh[1]);
                    mma16816(acc[mt][2 * g + 1], ah[mt], bh[2], bh[3]);
                    mma16816(acc[mt][2 * g + 1], ah[mt], bl[2], bl[3]);
                    mma16816(acc[mt][2 * g + 1], al[mt], bh[2], bh[3]);
                }
            }
        }
        __syncthreads();
    }

    const int gid = lane >> 2;
    const int tig = lane & 3;
#pragma unroll
    for (int mt = 0; mt < 2; mt++) {
        const int r0 = m0 + wm * 32 + mt * 16 + gid;
#pragma unroll
        for (int nf = 0; nf < 4; nf++) {
            const int col = n0 + wn * 32 + nf * 8 + 2 * tig;
            if (col < NC) {
                atomicAdd(out + (size_t)r0 * NC + col,       0.5f * acc[mt][nf][0]);
                atomicAdd(out + (size_t)r0 * NC + col + 1,   0.5f * acc[mt][nf][1]);
                atomicAdd(out + (size_t)(r0 + 8) * NC + col,     0.5f * acc[mt][nf][2]);
                atomicAdd(out + (size_t)(r0 + 8) * NC + col + 1, 0.5f * acc[mt][nf][3]);
            }
        }
    }
}

// =====================================================================
// launch
// =====================================================================
extern "C" void kernel_launch(void* const* d_in, const int* in_sizes, int n_in,
                              void* d_out, int out_size)
{
    const float* cls_token = (const float*)d_in[0];
    const float* x         = (const float*)d_in[1];
    const float* proj_w    = (const float*)d_in[2];
    const float* proj_b    = (const float*)d_in[3];
    const float* ln_g      = (const float*)d_in[4];
    const float* ln_b      = (const float*)d_in[5];
    const float* conv1_w   = (const float*)d_in[6];
    const float* conv2_w   = (const float*)d_in[7];
    const float* cls1_w    = (const float*)d_in[8];
    const float* cls1_b    = (const float*)d_in[9];
    const float* cls2_w    = (const float*)d_in[10];
    const float* cls2_b    = (const float*)d_in[11];
    float* out = (float*)d_out;

    cudaFuncSetAttribute(k_gemm_mma,
                         cudaFuncAttributeMaxDynamicSharedMemorySize, GEMM_SMEM);
    cudaFuncSetAttribute(k_cov_mma,
                         cudaFuncAttributeMaxDynamicSharedMemorySize, COV_SMEM);
    cudaFuncSetAttribute(k_conv,
                         cudaFuncAttributeMaxDynamicSharedMemorySize, CONV_SMEM);
    cudaFuncSetAttribute(k_head_mma,
                         cudaFuncAttributeMaxDynamicSharedMemorySize, HEAD_SMEM);

    k_convA<<<2048, 256>>>(x);                                      // 0
    k_convW<<<dim3(HD / 32, D_ / 32), 256>>>(proj_w);               // 1
    k_convH<<<2048, 256>>>(cls1_w, cls2_w, cls_token,
                           cls1_b, cls2_b, out);                    // 2
    k_gemm_mma<<<dim3(392, 2), 256, GEMM_SMEM>>>(proj_b);           // 3 <- ncu probe
    k_lnc<<<NH * B_, 256>>>(ln_g, ln_b);                            // 4
    k_cov_mma<<<dim3(3, B_), 256, COV_SMEM>>>();                    // 5
    k_conv<<<B_, 256, CONV_SMEM>>>(conv1_w, conv2_w);               // 6
    k_head_mma<<<dim3(4, 8, 4), 256, HEAD_SMEM>>>(out);             // 7
}

// round 14
// speedup vs baseline: 1.1019x; 1.1019x over previous
#include <cuda_runtime.h>
#include <cuda_bf16.h>
#include <cuda_fp16.h>
#include <math.h>
#include <stdint.h>

// ---------------- problem constants ----------------
#define B_    256
#define L_    197
#define LP    196
#define D_    768
#define HD    512
#define DH    128
#define NH    4
#define NC    1000
#define FLATN 2883   // 3*31*31
#define FPAD  2944   // flat padded to multiple of 32
#define NPAD  1024   // classifier N padded
#define HK_CLS_CHUNKS  24          // 768/32
#define HK_CHUNKS      116         // 24 + 92
#define HK_SPLIT       29          // chunks per k-split (116/4)

// ---------------- scratch (static __device__, no allocation) ----------------
__device__ __half g_xph[(size_t)B_ * LP * HD];        // 50176 x 512 (fp16)
__device__ float g_cov[(size_t)B_ * 3 * DH * DH];     // (b,p,d,e) NCHW

// fp16 buffers for tensor-core projection GEMM (single-pass: hi only)
__device__ __half gA_h[(size_t)B_ * LP * D_];    // [50176,768]
__device__ __half gWt_h[(size_t)HD * D_];        // [512,768]  W^T

// LN output (UNcentered) fp16 hi, natural layout (h,b, l=196, d=128)
__device__ __half gHn_h[(size_t)NH * B_ * LP * DH];
__device__ float gSh[(size_t)NH * B_ * DH];   // sum_l hi(hn)  (per column)
__device__ float gM [(size_t)NH * B_];        // tile mean (exact)

// classifier-head fp16 buffers (3-pass: hi+lo kept for accuracy)
__device__ __half gW1_h[(size_t)D_ * NPAD];      // [768,1024]
__device__ __half gW1_l[(size_t)D_ * NPAD];
__device__ __half gW2_h[(size_t)FPAD * NPAD];    // [2944,1024]
__device__ __half gW2_l[(size_t)FPAD * NPAD];
__device__ __half gCls_h[(size_t)B_ * D_];       // [256,768]
__device__ __half gCls_l[(size_t)B_ * D_];
__device__ __half gF_h[(size_t)B_ * FPAD];       // [256,2944]
__device__ __half gF_l[(size_t)B_ * FPAD];

// ---------------- baseline-PTX helpers ----------------
__device__ __forceinline__ uint32_t smem_u32(const void* p) {
    uint32_t a;
    asm("{ .reg .u64 t; cvta.to.shared.u64 t, %1; cvt.u32.u64 %0, t; }"
        : "=r"(a) : "l"(p));
    return a;
}
__device__ __forceinline__ void cp16(uint32_t dst, const void* src) {
    asm volatile("cp.async.ca.shared.global [%0], [%1], 16;"
                 :: "r"(dst), "l"(src) : "memory");
}
#define CP_COMMIT() asm volatile("cp.async.commit_group;" ::: "memory")
#define CP_WAIT0()  asm volatile("cp.async.wait_group 0;" ::: "memory")
#define CP_WAIT1()  asm volatile("cp.async.wait_group 1;" ::: "memory")

__device__ __forceinline__ void ldx4(uint32_t* r, uint32_t addr) {
    asm volatile("ldmatrix.sync.aligned.m8n8.x4.shared.b16 {%0,%1,%2,%3}, [%4];"
                 : "=r"(r[0]), "=r"(r[1]), "=r"(r[2]), "=r"(r[3]) : "r"(addr));
}
__device__ __forceinline__ void ldx4t(uint32_t* r, uint32_t addr) {
    asm volatile("ldmatrix.sync.aligned.m8n8.x4.trans.shared.b16 {%0,%1,%2,%3}, [%4];"
                 : "=r"(r[0]), "=r"(r[1]), "=r"(r[2]), "=r"(r[3]) : "r"(addr));
}
__device__ __forceinline__ void mma16816(float* c, const uint32_t* a,
                                         uint32_t b0, uint32_t b1) {
    asm volatile(
        "mma.sync.aligned.m16n8k16.row.col.f32.f16.f16.f32 "
        "{%0,%1,%2,%3}, {%4,%5,%6,%7}, {%8,%9}, {%0,%1,%2,%3};"
        : "+f"(c[0]), "+f"(c[1]), "+f"(c[2]), "+f"(c[3])
        : "r"(a[0]), "r"(a[1]), "r"(a[2]), "r"(a[3]), "r"(b0), "r"(b1));
}

// =====================================================================
// K0a: round x[:,1:,:] to fp16  [50176,768]
// =====================================================================
__global__ void __launch_bounds__(256) k_convA(const float* __restrict__ X)
{
    const int total = B_ * LP * (D_ / 4);
    for (int i = blockIdx.x * blockDim.x + threadIdx.x; i < total;
         i += gridDim.x * blockDim.x) {
        const int m  = i / (D_ / 4);
        const int k4 = i - m * (D_ / 4);
        const int b  = m / LP;
        const int l  = m - b * LP + 1;
        float4 v = *(const float4*)(X + ((size_t)(b * L_ + l)) * D_ + k4 * 4);
        __half2 h01, h23;
        h01.x = __float2half_rn(v.x); h01.y = __float2half_rn(v.y);
        h23.x = __float2half_rn(v.z); h23.y = __float2half_rn(v.w);
        ((__half2*)gA_h)[(size_t)i * 2]     = h01;
        ((__half2*)gA_h)[(size_t)i * 2 + 1] = h23;
    }
}

// =====================================================================
// K0b: W [768,512] -> W^T fp16 [512,768] (hi only; single-pass GEMM)
// =====================================================================
__global__ void __launch_bounds__(256) k_convW(const float* __restrict__ W)
{
    __shared__ float t[32][33];
    const int nb = blockIdx.x * 32;
    const int kb = blockIdx.y * 32;
    const int tx = threadIdx.x & 31, ty = threadIdx.x >> 5;
#pragma unroll
    for (int r = 0; r < 32; r += 8)
        t[ty + r][tx] = W[(size_t)(kb + ty + r) * HD + nb + tx];
    __syncthreads();
#pragma unroll
    for (int r = 0; r < 32; r += 8)
        gWt_h[(size_t)(nb + ty + r) * D_ + kb + tx] = __float2half_rn(t[tx][ty + r]);
}

// =====================================================================
// K0c: head-weight conversions + out init
// =====================================================================
#define CH_S1 (D_ * NPAD)
#define CH_S2 ((size_t)FPAD * NPAD)
#define CH_S3 (B_ * D_)
#define CH_S4 (B_ * NC)
#define CH_TOTAL (CH_S1 + CH_S2 + CH_S3 + CH_S4)

__global__ void __launch_bounds__(256) k_convH(
    const float* __restrict__ w1, const float* __restrict__ w2,
    const float* __restrict__ cls, const float* __restrict__ b1,
    const float* __restrict__ b2, float* __restrict__ out)
{
    for (size_t i = (size_t)blockIdx.x * 256 + threadIdx.x; i < CH_TOTAL;
         i += (size_t)gridDim.x * 256) {
        if (i < CH_S1) {
            const int r = (int)(i >> 10), c = (int)(i & 1023);
            float v = (c < NC) ? w1[(size_t)r * NC + c] : 0.f;
            const __half h = __float2half_rn(v);
            gW1_h[i] = h;
            gW1_l[i] = __float2half_rn(v - __half2float(h));
        } else if (i < CH_S1 + CH_S2) {
            const size_t j = i - CH_S1;
            const int r = (int)(j >> 10), c = (int)(j & 1023);
            float v = (r < FLATN && c < NC) ? w2[(size_t)r * NC + c] : 0.f;
            const __half h = __float2half_rn(v);
            gW2_h[j] = h;
            gW2_l[j] = __float2half_rn(v - __half2float(h));
        } else if (i < CH_S1 + CH_S2 + CH_S3) {
            const size_t j = i - CH_S1 - CH_S2;
            float v = cls[j];
            const __half h = __float2half_rn(v);
            gCls_h[j] = h;
            gCls_l[j] = __float2half_rn(v - __half2float(h));
        } else {
            const size_t j = i - CH_S1 - CH_S2 - CH_S3;
            const int n = (int)(j % NC);
            out[j] = 0.5f * (b1[n] + b2[n]);
        }
    }
}

// =====================================================================
// K1: warp-mma fp16 single-pass GEMM: xp = A_h @ B_h    <- ncu probe
// R12-proven config: CTA 128x128, block=128 (4 warps), warp tile 64x64,
// grid 392x4, 2-stage cp.async. fp16 epilogue (R13's one good change).
// =====================================================================
#define RSB      80
#define TILE_B   (128 * RSB)
#define OFF_AH   0
#define OFF_BH   (1 * TILE_B)
#define STAGE_B  (2 * TILE_B)          // 20480
#define GEMM_SMEM (2 * STAGE_B)        // 40960
#define NCHUNK   (D_ / 32)             // 24

__device__ __forceinline__ void gemm_load_stage(
    uint32_t sb, int buf, int c, int m0, int n0, int tid)
{
    const int k0 = c * 32;
    const uint32_t stg = sb + buf * STAGE_B;
#pragma unroll
    for (int q = 0; q < 4; q++) {
        const int ch  = q * 128 + tid;      // 0..511 (16B units per tile)
        const int row = ch >> 2;
        const int cc  = ch & 3;
        const uint32_t doff = (uint32_t)row * RSB + cc * 16;
        const size_t ga = (size_t)(m0 + row) * D_ + k0 + cc * 8;
        const size_t gb = (size_t)(n0 + row) * D_ + k0 + cc * 8;
        cp16(stg + OFF_AH + doff, gA_h + ga);
        cp16(stg + OFF_BH + doff, gWt_h + gb);
    }
}

__global__ void __launch_bounds__(128) k_gemm_mma(const float* __restrict__ bias)
{
    extern __shared__ char smem[];
    const uint32_t sb = smem_u32(smem);
    const int tid  = threadIdx.x;
    const int wid  = tid >> 5;
    const int lane = tid & 31;
    const int wm = wid >> 1;              // 0..1 (m 64 each)
    const int wn = wid & 1;               // 0..1 (n 64 each)
    const int m0 = blockIdx.x * 128;
    const int n0 = blockIdx.y * 128;

    const uint32_t a_row = (lane & 15);
    const uint32_t a_col = (uint32_t)(lane >> 4) * 16;
    const uint32_t b_row = (lane & 7) + ((lane >> 4) << 3);
    const uint32_t b_col = (uint32_t)((lane >> 3) & 1) * 16;

    uint32_t a_off[4], b_off[4];
#pragma unroll
    for (int mt = 0; mt < 4; mt++)
        a_off[mt] = (uint32_t)(wm * 64 + mt * 16 + a_row) * RSB + a_col;
#pragma unroll
    for (int g = 0; g < 4; g++)
        b_off[g] = (uint32_t)(wn * 64 + g * 16 + b_row) * RSB + b_col;

    float acc[4][8][4];
#pragma unroll
    for (int mt = 0; mt < 4; mt++)
#pragma unroll
        for (int nt = 0; nt < 8; nt++)
#pragma unroll
            for (int e = 0; e < 4; e++) acc[mt][nt][e] = 0.f;

    gemm_load_stage(sb, 0, 0, m0, n0, tid);
    CP_COMMIT();

    for (int c = 0; c < NCHUNK; c++) {
        if (c + 1 < NCHUNK) {
            gemm_load_stage(sb, (c + 1) & 1, c + 1, m0, n0, tid);
            CP_COMMIT();
            CP_WAIT1();
        } else {
            CP_WAIT0();
        }
        __syncthreads();

        const uint32_t stg = sb + (c & 1) * STAGE_B;
#pragma unroll
        for (int ks = 0; ks < 2; ks++) {
            const uint32_t kb = (uint32_t)ks * 32;
            uint32_t ah[4][4];
#pragma unroll
            for (int mt = 0; mt < 4; mt++)
                ldx4(ah[mt], stg + OFF_AH + a_off[mt] + kb);
#pragma unroll
            for (int g = 0; g < 4; g++) {
                uint32_t bh[4];
                ldx4(bh, stg + OFF_BH + b_off[g] + kb);
#pragma unroll
                for (int mt = 0; mt < 4; mt++)
                    mma16816(acc[mt][2 * g],     ah[mt], bh[0], bh[1]);
#pragma unroll
                for (int mt = 0; mt < 4; mt++)
                    mma16816(acc[mt][2 * g + 1], ah[mt], bh[2], bh[3]);
            }
        }
        __syncthreads();
    }

    const int gid = lane >> 2;
    const int tig = lane & 3;
#pragma unroll
    for (int mt = 0; mt < 4; mt++) {
        const int r0 = m0 + wm * 64 + mt * 16 + gid;
#pragma unroll
        for (int nt = 0; nt < 8; nt++) {
            const int col = n0 + wn * 64 + nt * 8 + 2 * tig;
            const float b0 = bias[col], b1v = bias[col + 1];
            __half2 v0, v1;
            v0.x = __float2half_rn(acc[mt][nt][0] + b0);
            v0.y = __float2half_rn(acc[mt][nt][1] + b1v);
            v1.x = __float2half_rn(acc[mt][nt][2] + b0);
            v1.y = __float2half_rn(acc[mt][nt][3] + b1v);
            *(__half2*)(g_xph + (size_t)r0 * HD + col)       = v0;
            *(__half2*)(g_xph + (size_t)(r0 + 8) * HD + col) = v1;
        }
    }
}

// =====================================================================
// K2: streaming LayerNorm (reads fp16 xp) -> fp16 hi + column sums +
// exact tile mean (centering folded into cov as rank-1 correction)
// =====================================================================
__global__ void __launch_bounds__(256) k_lnc(
    const float* __restrict__ g, const float* __restrict__ be)
{
    __shared__ float smh[8][128];
    __shared__ float smf[8][128];

    const int h = blockIdx.x >> 8;
    const int b = blockIdx.x & 255;
    const int tid  = threadIdx.x;
    const int warp = tid >> 5;
    const int lane = tid & 31;

    const float4 gv = *(const float4*)(g + lane * 4);
    const float4 bv = *(const float4*)(be + lane * 4);

    __half* dst_h = gHn_h + ((size_t)(h * B_ + b)) * LP * DH;

    float sh0 = 0.f, sh1 = 0.f, sh2 = 0.f, sh3 = 0.f;
    float sf0 = 0.f, sf1 = 0.f, sf2 = 0.f, sf3 = 0.f;

    for (int l = warp; l < LP; l += 8) {
        const __half* src = g_xph + ((size_t)(b * LP + l)) * HD + h * DH;
        const uint2 u = *(const uint2*)(src + lane * 4);
        const __half2 p01 = *(const __half2*)&u.x;
        const __half2 p23 = *(const __half2*)&u.y;
        const float x0 = __half2float(p01.x), x1 = __half2float(p01.y);
        const float x2 = __half2float(p23.x), x3 = __half2float(p23.y);

        float s = x0 + x1 + x2 + x3;
#pragma unroll
        for (int o = 16; o; o >>= 1) s += __shfl_xor_sync(0xffffffffu, s, o);
        const float mu = s * (1.0f / 128.0f);

        const float d0 = x0 - mu, d1 = x1 - mu, d2 = x2 - mu, d3 = x3 - mu;
        float sq = d0 * d0 + d1 * d1 + d2 * d2 + d3 * d3;
#pragma unroll
        for (int o = 16; o; o >>= 1) sq += __shfl_xor_sync(0xffffffffu, sq, o);
        const float rstd = rsqrtf(sq * (1.0f / 128.0f) + 1e-5f);

        const float o0 = d0 * rstd * gv.x + bv.x;
        const float o1 = d1 * rstd * gv.y + bv.y;
        const float o2 = d2 * rstd * gv.z + bv.z;
        const float o3 = d3 * rstd * gv.w + bv.w;

        const __half h0 = __float2half_rn(o0);
        const __half h1 = __float2half_rn(o1);
        const __half h2 = __float2half_rn(o2);
        const __half h3 = __float2half_rn(o3);
        __half2 hh01; hh01.x = h0; hh01.y = h1;
        __half2 hh23; hh23.x = h2; hh23.y = h3;

        const size_t ro = (size_t)l * DH + lane * 4;
        *(__half2*)(dst_h + ro)     = hh01;
        *(__half2*)(dst_h + ro + 2) = hh23;

        sh0 += __half2float(h0); sh1 += __half2float(h1);
        sh2 += __half2float(h2); sh3 += __half2float(h3);
        sf0 += o0; sf1 += o1; sf2 += o2; sf3 += o3;
    }
    smh[warp][lane * 4 + 0] = sh0; smh[warp][lane * 4 + 1] = sh1;
    smh[warp][lane * 4 + 2] = sh2; smh[warp][lane * 4 + 3] = sh3;
    smf[warp][lane * 4 + 0] = sf0; smf[warp][lane * 4 + 1] = sf1;
    smf[warp][lane * 4 + 2] = sf2; smf[warp][lane * 4 + 3] = sf3;
    __syncthreads();

    if (tid < 128) {
        float th = 0.f, tf = 0.f;
#pragma unroll
        for (int w = 0; w < 8; w++) { th += smh[w][tid]; tf += smf[w][tid]; }
        gSh[(size_t)(h * B_ + b) * DH + tid] = th;
        smf[0][tid] = tf;
    }
    __syncthreads();
    if (tid < 32) {
        float t = smf[0][tid] + smf[0][tid + 32] + smf[0][tid + 64] + smf[0][tid + 96];
#pragma unroll
        for (int o = 16; o; o >>= 1) t += __shfl_xor_sync(0xffffffffu, t, o);
        if (tid == 0) gM[h * B_ + b] = t * (1.0f / (LP * DH));
    }
}

// =====================================================================
// K3: cov via fp16 mma single-pass, trans-ldmatrix, rank-1 centering
// =====================================================================
#define CRS2   136
#define CRSB2  (CRS2 * 2)               // 272 B
#define CTILE2 (208 * CRSB2)            // 56576
#define COV_SMEM (2 * CTILE2)           // 113,152

__global__ void __launch_bounds__(256) k_cov_mma()
{
    extern __shared__ char csm[];
    const uint32_t sb = smem_u32(csm);
    __shared__ float colsq[DH];
    __shared__ float s1s[DH];
    __shared__ float s2s[DH];

    const int p = blockIdx.x;
    const int b = blockIdx.y;
    const int tid  = threadIdx.x;
    const int wid  = tid >> 5;
    const int lane = tid & 31;
    const int wm = wid >> 1;
    const int wn = wid & 1;

    const __half* Asrc = gHn_h + ((size_t)(p * B_ + b)) * LP * DH;
    const __half* Bhs  = gHn_h + ((size_t)((p + 1) * B_ + b)) * LP * DH;

    const uint32_t tA = sb, tBh = sb + CTILE2;

    for (int i = tid; i < 2 * 12 * 17; i += 256) {
        const int tile = i / 204;
        const int rem  = i % 204;
        const int r    = rem / 17;
        const int c    = rem % 17;
        *(uint4*)(csm + (size_t)tile * CTILE2 + (196 + r) * CRSB2 + c * 16) =
            make_uint4(0u, 0u, 0u, 0u);
    }
    for (int t = tid; t < LP * 16; t += 256) {
        const int row = t >> 4;
        const int ch  = t & 15;
        const uint32_t doff = (uint32_t)row * CRSB2 + ch * 16;
        const size_t   goff = (size_t)row * DH + ch * 8;
        cp16(tA  + doff, Asrc + goff);
        cp16(tBh + doff, Bhs + goff);
    }
    CP_COMMIT();
    if (tid < DH) {
        colsq[tid] = 0.f;
        s1s[tid] = gSh[(size_t)(p * B_ + b) * DH + tid];
        s2s[tid] = gSh[(size_t)((p + 1) * B_ + b) * DH + tid];
    }
    CP_WAIT0();
    __syncthreads();

    const uint32_t ar = (lane & 7) + ((lane >> 4) << 3);
    const uint32_t ac = ((lane >> 3) & 1) * 16;
    const uint32_t br = (lane & 7) + (((lane >> 3) & 1) << 3);
    const uint32_t bc = (uint32_t)(lane >> 4) * 16;

    uint32_t a_off[2], b_off[4];
#pragma unroll
    for (int mt = 0; mt < 2; mt++)
        a_off[mt] = ar * CRSB2 + (uint32_t)(wm * 32 + mt * 16) * 2 + ac;
#pragma unroll
    for (int g = 0; g < 4; g++)
        b_off[g] = br * CRSB2 + (uint32_t)(wn * 64 + g * 16) * 2 + bc;

    float acc[2][8][4];
#pragma unroll
    for (int mt = 0; mt < 2; mt++)
#pragma unroll
        for (int nt = 0; nt < 8; nt++)
#pragma unroll
            for (int e = 0; e < 4; e++) acc[mt][nt][e] = 0.f;

#pragma unroll
    for (int ks = 0; ks < 13; ks++) {
        const uint32_t kb = (uint32_t)ks * 16 * CRSB2;
        uint32_t ah[2][4];
#pragma unroll
        for (int mt = 0; mt < 2; mt++)
            ldx4t(ah[mt], tA + a_off[mt] + kb);
#pragma unroll
        for (int g = 0; g < 4; g++) {
            uint32_t bh[4];
            ldx4t(bh, tBh + b_off[g] + kb);
#pragma unroll
            for (int mt = 0; mt < 2; mt++) {
                mma16816(acc[mt][2 * g],     ah[mt], bh[0], bh[1]);
                mma16816(acc[mt][2 * g + 1], ah[mt], bh[2], bh[3]);
            }
        }
    }

    const float m1 = gM[p * B_ + b];
    const float m2 = gM[(p + 1) * B_ + b];
    const float c12 = (float)LP * m1 * m2;
    const int gid = lane >> 2;
    const int tig = lane & 3;
#pragma unroll
    for (int mt = 0; mt < 2; mt++) {
        const int d0 = wm * 32 + mt * 16 + gid;
        const float t1a = m2 * s1s[d0]     - c12;
        const float t1b = m2 * s1s[d0 + 8] - c12;
#pragma unroll
        for (int nt = 0; nt < 8; nt++) {
            const int e0 = wn * 64 + nt * 8 + 2 * tig;
            const float t2a = m1 * s2s[e0];
            const float t2b = m1 * s2s[e0 + 1];
            acc[mt][nt][0] -= t1a + t2a;
            acc[mt][nt][1] -= t1a + t2b;
            acc[mt][nt][2] -= t1b + t2a;
            acc[mt][nt][3] -= t1b + t2b;
        }
    }

#pragma unroll
    for (int nt = 0; nt < 8; nt++) {
        float s0 = acc[0][nt][0] * acc[0][nt][0] + acc[0][nt][2] * acc[0][nt][2]
                 + acc[1][nt][0] * acc[1][nt][0] + acc[1][nt][2] * acc[1][nt][2];
        float s1 = acc[0][nt][1] * acc[0][nt][1] + acc[0][nt][3] * acc[0][nt][3]
                 + acc[1][nt][1] * acc[1][nt][1] + acc[1][nt][3] * acc[1][nt][3];
#pragma unroll
        for (int o = 4; o <= 16; o <<= 1) {
            s0 += __shfl_xor_sync(0xffffffffu, s0, o);
            s1 += __shfl_xor_sync(0xffffffffu, s1, o);
        }
        if (lane < 4) {
            const int col = wn * 64 + nt * 8 + 2 * lane;
            atomicAdd(&colsq[col], s0);
            atomicAdd(&colsq[col + 1], s1);
        }
    }
    __syncthreads();

    float* outb = g_cov + ((size_t)(b * 3 + p)) * (DH * DH);
#pragma unroll
    for (int nt = 0; nt < 8; nt++) {
        const int col = wn * 64 + nt * 8 + 2 * tig;
        const float i0 = 1.0f / fmaxf(sqrtf(colsq[col]),     (float)LP * 1e-12f);
        const float i1 = 1.0f / fmaxf(sqrtf(colsq[col + 1]), (float)LP * 1e-12f);
#pragma unroll
        for (int mt = 0; mt < 2; mt++) {
            const int r0 = wm * 32 + mt * 16 + gid;
            float2 v0 = make_float2(acc[mt][nt][0] * i0, acc[mt][nt][1] * i1);
            float2 v1 = make_float2(acc[mt][nt][2] * i0, acc[mt][nt][3] * i1);
            *(float2*)(outb + (size_t)r0 * DH + col)       = v0;
            *(float2*)(outb + (size_t)(r0 + 8) * DH + col) = v1;
        }
    }
}

// =====================================================================
// K4: fused conv1 -> GELU -> conv2 ; emits flat as fp16 hi/lo (padded)
// =====================================================================
#define CONV_CS_B  (3 * 66 * 128 * 4)
#define CONV_SMEM  (CONV_CS_B + 3 * 3969 * 4)  // 149,004

__global__ void __launch_bounds__(256) k_conv(
    const float* __restrict__ w1, const float* __restrict__ w2)
{
    extern __shared__ char cvsm[];
    float* cs = (float*)cvsm;
    float* z1 = (float*)(cvsm + CONV_CS_B);
    __shared__ float w1s[81];
    __shared__ float w2s[81];

    const int b = blockIdx.x;
    const int tid = threadIdx.x;
    if (tid < 81) { w1s[tid] = w1[tid]; w2s[tid] = w2[tid]; }

    const float* cb = g_cov + (size_t)b * 3 * DH * DH;

#pragma unroll 1
    for (int ph = 0; ph < 2; ph++) {
        const int r0 = ph * 64;
        const int nr = ph ? 64 : 66;
        const int y0 = ph ? 32 : 0;
        const int ny = ph ? 31 : 32;
        __syncthreads();
        for (int i = tid; i < 3 * nr * 32; i += 256) {
            const int c  = i / (nr * 32);
            const int rr = (i / 32) % nr;
            const int q  = i % 32;
            *(float4*)(cs + (c * 66 + rr) * 128 + q * 4) =
                *(const float4*)(cb + (size_t)c * (DH * DH) + (r0 + rr) * DH + q * 4);
        }
        __syncthreads();
        for (int idx = tid; idx < 3 * ny * 63; idx += 256) {
            const int c = idx / (ny * 63);
            const int r = idx % (ny * 63);
            const int y = y0 + r / 63;
            const int x = r % 63;
            float s = 0.f;
#pragma unroll
            for (int ci = 0; ci < 3; ci++)
#pragma unroll
                for (int ky = 0; ky < 3; ky++)
#pragma unroll
                    for (int kx = 0; kx < 3; kx++)
                        s += cs[(ci * 66 + (2 * y + ky - r0)) * 128 + 2 * x + kx]
                           * w1s[((c * 3 + ci) * 3 + ky) * 3 + kx];
            s = 0.5f * s * (1.0f + erff(s * 0.70710678118654752f));
            z1[c * 3969 + y * 63 + x] = s;
        }
    }
    __syncthreads();

    __half* fh = gF_h + (size_t)b * FPAD;
    __half* fl = gF_l + (size_t)b * FPAD;
    for (int idx = tid; idx < FLATN; idx += 256) {
        const int c = idx / 961;
        const int r = idx % 961;
        const int y = r / 31, x = r % 31;
        float s = 0.f;
#pragma unroll
        for (int ci = 0; ci < 3; ci++)
#pragma unroll
            for (int ky = 0; ky < 3; ky++)
#pragma unroll
                for (int kx = 0; kx < 3; kx++)
                    s += z1[ci * 3969 + (2 * y + ky) * 63 + (2 * x + kx)]
                       * w2s[((c * 3 + ci) * 3 + ky) * 3 + kx];
        const __half hv = __float2half_rn(s);
        fh[idx] = hv;
        fl[idx] = __float2half_rn(s - __half2float(hv));
    }
    for (int idx = FLATN + tid; idx < FPAD; idx += 256) {
        fh[idx] = __float2half_rn(0.f);
        fl[idx] = __float2half_rn(0.f);
    }
}

// =====================================================================
// K5: classifier head via fp16 mma, 3-pass split, k-split=4 + atomicAdd
// =====================================================================
#define HRSB   80
#define HBRS   272
#define OFF_AH2 0
#define OFF_AL2 (64 * HRSB)
#define OFF_BH2 (2 * 64 * HRSB)
#define OFF_BL2 (OFF_BH2 + 32 * HBRS)
#define HSTAGE  (OFF_BL2 + 32 * HBRS)   // 27648
#define HEAD_SMEM (2 * HSTAGE)          // 55296

__device__ __forceinline__ void head_load_stage(
    uint32_t sb, int buf, int chunk, int m0, int n0, int tid)
{
    const uint32_t stg = sb + buf * HSTAGE;
    const bool in_cls = (chunk < HK_CLS_CHUNKS);
    const int  kr     = in_cls ? chunk * 32 : (chunk - HK_CLS_CHUNKS) * 32;
    const __half* Ah = in_cls ? gCls_h : gF_h;
    const __half* Al = in_cls ? gCls_l : gF_l;
    const __half* Bh = in_cls ? gW1_h  : gW2_h;
    const __half* Bl = in_cls ? gW1_l  : gW2_l;
    const int astr = in_cls ? D_ : FPAD;

    {
        const int idx = tid;
        const int row = idx >> 2;
        const int q   = idx & 3;
        const uint32_t doff = (uint32_t)row * HRSB + q * 16;
        const size_t goff = (size_t)(m0 + row) * astr + kr + q * 8;
        cp16(stg + OFF_AH2 + doff, Ah + goff);
        cp16(stg + OFF_AL2 + doff, Al + goff);
    }
#pragma unroll
    for (int j = 0; j < 2; j++) {
        const int idx = j * 256 + tid;
        const int row = idx >> 4;
        const int q   = idx & 15;
        const uint32_t doff = (uint32_t)row * HBRS + q * 16;
        const size_t goff = (size_t)(kr + row) * NPAD + n0 + q * 8;
        cp16(stg + OFF_BH2 + doff, Bh + goff);
        cp16(stg + OFF_BL2 + doff, Bl + goff);
    }
}

__global__ void __launch_bounds__(256) k_head_mma(float* __restrict__ out)
{
    extern __shared__ char hsm[];
    const uint32_t sb = smem_u32(hsm);
    const int tid  = threadIdx.x;
    const int wid  = tid >> 5;
    const int lane = tid & 31;
    const int wm = wid >> 2;
    const int wn = wid & 3;
    const int m0 = blockIdx.x * 64;
    const int n0 = blockIdx.y * 128;
    const int c0 = blockIdx.z * HK_SPLIT;

    const uint32_t a_row = (lane & 15);
    const uint32_t a_col = (uint32_t)(lane >> 4) * 16;
    const uint32_t br = (lane & 7) + (((lane >> 3) & 1) << 3);
    const uint32_t bc = (uint32_t)(lane >> 4) * 16;

    uint32_t a_off[2], b_off[2];
#pragma unroll
    for (int mt = 0; mt < 2; mt++)
        a_off[mt] = (uint32_t)(wm * 32 + mt * 16 + a_row) * HRSB + a_col;
#pragma unroll
    for (int g = 0; g < 2; g++)
        b_off[g] = br * HBRS + (uint32_t)(wn * 32 + g * 16) * 2 + bc;

    float acc[2][4][4];
#pragma unroll
    for (int mt = 0; mt < 2; mt++)
#pragma unroll
        for (int nf = 0; nf < 4; nf++)
#pragma unroll
            for (int e = 0; e < 4; e++) acc[mt][nf][e] = 0.f;

    head_load_stage(sb, 0, c0, m0, n0, tid);
    CP_COMMIT();

    for (int i = 0; i < HK_SPLIT; i++) {
        if (i + 1 < HK_SPLIT) {
            head_load_stage(sb, (i + 1) & 1, c0 + i + 1, m0, n0, tid);
            CP_COMMIT();
            CP_WAIT1();
        } else {
            CP_WAIT0();
        }
        __syncthreads();

        const uint32_t stg = sb + (i & 1) * HSTAGE;
#pragma unroll
        for (int ks = 0; ks < 2; ks++) {
            uint32_t ah[2][4], al[2][4];
#pragma unroll
            for (int mt = 0; mt < 2; mt++) {
                ldx4(ah[mt], stg + OFF_AH2 + a_off[mt] + ks * 32);
                ldx4(al[mt], stg + OFF_AL2 + a_off[mt] + ks * 32);
            }
            const uint32_t kbb = (uint32_t)ks * 16 * HBRS;
#pragma unroll
            for (int g = 0; g < 2; g++) {
                uint32_t bh[4], bl[4];
                ldx4t(bh, stg + OFF_BH2 + b_off[g] + kbb);
                ldx4t(bl, stg + OFF_BL2 + b_off[g] + kbb);
#pragma unroll
                for (int mt = 0; mt < 2; mt++) {
                    mma16816(acc[mt][2 * g],     ah[mt], bh[0], bh[1]);
                    mma16816(acc[mt][2 * g],     ah[mt], bl[0], bl[1]);
                    mma16816(acc[mt][2 * g],     al[mt], bh[0], bh[1]);
                    mma16816(acc[mt][2 * g + 1], ah[mt], bh[2], bh[3]);
                    mma16816(acc[mt][2 * g + 1], ah[mt], bl[2], bl[3]);
                    mma16816(acc[mt][2 * g + 1], al[mt], bh[2], bh[3]);
                }
            }
        }
        __syncthreads();
    }

    const int gid = lane >> 2;
    const int tig = lane & 3;
#pragma unroll
    for (int mt = 0; mt < 2; mt++) {
        const int r0 = m0 + wm * 32 + mt * 16 + gid;
#pragma unroll
        for (int nf = 0; nf < 4; nf++) {
            const int col = n0 + wn * 32 + nf * 8 + 2 * tig;
            if (col < NC) {
                atomicAdd(out + (size_t)r0 * NC + col,       0.5f * acc[mt][nf][0]);
                atomicAdd(out + (size_t)r0 * NC + col + 1,   0.5f * acc[mt][nf][1]);
                atomicAdd(out + (size_t)(r0 + 8) * NC + col,     0.5f * acc[mt][nf][2]);
                atomicAdd(out + (size_t)(r0 + 8) * NC + col + 1, 0.5f * acc[mt][nf][3]);
            }
        }
    }
}

// =====================================================================
// launch
// =====================================================================
extern "C" void kernel_launch(void* const* d_in, const int* in_sizes, int n_in,
                              void* d_out, int out_size)
{
    const float* cls_token = (const float*)d_in[0];
    const float* x         = (const float*)d_in[1];
    const float* proj_w    = (const float*)d_in[2];
    const float* proj_b    = (const float*)d_in[3];
    const float* ln_g      = (const float*)d_in[4];
    const float* ln_b      = (const float*)d_in[5];
    const float* conv1_w   = (const float*)d_in[6];
    const float* conv2_w   = (const float*)d_in[7];
    const float* cls1_w    = (const float*)d_in[8];
    const float* cls1_b    = (const float*)d_in[9];
    const float* cls2_w    = (const float*)d_in[10];
    const float* cls2_b    = (const float*)d_in[11];
    float* out = (float*)d_out;

    cudaFuncSetAttribute(k_gemm_mma,
                         cudaFuncAttributeMaxDynamicSharedMemorySize, GEMM_SMEM);
    cudaFuncSetAttribute(k_cov_mma,
                         cudaFuncAttributeMaxDynamicSharedMemorySize, COV_SMEM);
    cudaFuncSetAttribute(k_conv,
                         cudaFuncAttributeMaxDynamicSharedMemorySize, CONV_SMEM);
    cudaFuncSetAttribute(k_head_mma,
                         cudaFuncAttributeMaxDynamicSharedMemorySize, HEAD_SMEM);

    k_convA<<<2048, 256>>>(x);                                      // 0
    k_convW<<<dim3(HD / 32, D_ / 32), 256>>>(proj_w);               // 1
    k_convH<<<2048, 256>>>(cls1_w, cls2_w, cls_token,
                           cls1_b, cls2_b, out);                    // 2
    k_gemm_mma<<<dim3(392, 4), 128, GEMM_SMEM>>>(proj_b);           // 3 <- ncu probe
    k_lnc<<<NH * B_, 256>>>(ln_g, ln_b);                            // 4
    k_cov_mma<<<dim3(3, B_), 256, COV_SMEM>>>();                    // 5
    k_conv<<<B_, 256, CONV_SMEM>>>(conv1_w, conv2_w);               // 6
    k_head_mma<<<dim3(4, 8, 4), 256, HEAD_SMEM>>>(out);             // 7
}

// round 16
// speedup vs baseline: 1.1361x; 1.0310x over previous
#include <cuda_runtime.h>
#include <cuda_bf16.h>
#include <cuda_fp16.h>
#include <math.h>
#include <stdint.h>

// ---------------- problem constants ----------------
#define B_    256
#define L_    197
#define LP    196
#define D_    768
#define HD    512
#define DH    128
#define NH    4
#define NC    1000
#define FLATN 2883   // 3*31*31
#define FPAD  2944   // flat padded to multiple of 32
#define NPAD  1024   // classifier N padded
#define HK_CLS_CHUNKS  24          // 768/32
#define HK_CHUNKS      116         // 24 + 92
#define HK_SPLIT       29          // chunks per k-split (116/4)

// ---------------- scratch (static __device__, no allocation) ----------------
__device__ float g_cov[(size_t)B_ * 3 * DH * DH];     // (b,p,d,e) NCHW

// fp16 buffers for tensor-core projection GEMM (single-pass: hi only)
__device__ __half gA_h[(size_t)B_ * LP * D_];    // [50176,768]
__device__ __half gWt_h[(size_t)HD * D_];        // [512,768]  W^T

// LN output (UNcentered) fp16, natural layout (h,b, l=196, d=128)
__device__ __half gHn_h[(size_t)NH * B_ * LP * DH];
__device__ float gSh[(size_t)NH * B_ * DH];   // sum_l fp16(hn) per column (atomic)
__device__ float gM [(size_t)NH * B_];        // raw sum of hn (atomic; /LP*DH later)

// classifier-head fp16 buffers (3-pass: hi+lo kept for accuracy)
__device__ __half gW1_h[(size_t)D_ * NPAD];      // [768,1024]
__device__ __half gW1_l[(size_t)D_ * NPAD];
__device__ __half gW2_h[(size_t)FPAD * NPAD];    // [2944,1024]
__device__ __half gW2_l[(size_t)FPAD * NPAD];
__device__ __half gCls_h[(size_t)B_ * D_];       // [256,768]
__device__ __half gCls_l[(size_t)B_ * D_];
__device__ __half gF_h[(size_t)B_ * FPAD];       // [256,2944]
__device__ __half gF_l[(size_t)B_ * FPAD];

// ---------------- baseline-PTX helpers ----------------
__device__ __forceinline__ uint32_t smem_u32(const void* p) {
    uint32_t a;
    asm("{ .reg .u64 t; cvta.to.shared.u64 t, %1; cvt.u32.u64 %0, t; }"
        : "=r"(a) : "l"(p));
    return a;
}
__device__ __forceinline__ void cp16(uint32_t dst, const void* src) {
    asm volatile("cp.async.ca.shared.global [%0], [%1], 16;"
                 :: "r"(dst), "l"(src) : "memory");
}
#define CP_COMMIT() asm volatile("cp.async.commit_group;" ::: "memory")
#define CP_WAIT0()  asm volatile("cp.async.wait_group 0;" ::: "memory")
#define CP_WAIT1()  asm volatile("cp.async.wait_group 1;" ::: "memory")

__device__ __forceinline__ void ldx4(uint32_t* r, uint32_t addr) {
    asm volatile("ldmatrix.sync.aligned.m8n8.x4.shared.b16 {%0,%1,%2,%3}, [%4];"
                 : "=r"(r[0]), "=r"(r[1]), "=r"(r[2]), "=r"(r[3]) : "r"(addr));
}
__device__ __forceinline__ void ldx4t(uint32_t* r, uint32_t addr) {
    asm volatile("ldmatrix.sync.aligned.m8n8.x4.trans.shared.b16 {%0,%1,%2,%3}, [%4];"
                 : "=r"(r[0]), "=r"(r[1]), "=r"(r[2]), "=r"(r[3]) : "r"(addr));
}
__device__ __forceinline__ void mma16816(float* c, const uint32_t* a,
                                         uint32_t b0, uint32_t b1) {
    asm volatile(
        "mma.sync.aligned.m16n8k16.row.col.f32.f16.f16.f32 "
        "{%0,%1,%2,%3}, {%4,%5,%6,%7}, {%8,%9}, {%0,%1,%2,%3};"
        : "+f"(c[0]), "+f"(c[1]), "+f"(c[2]), "+f"(c[3])
        : "r"(a[0]), "r"(a[1]), "r"(a[2]), "r"(a[3]), "r"(b0), "r"(b1));
}

// =====================================================================
// K0a: round x[:,1:,:] to fp16  [50176,768]
// =====================================================================
__global__ void __launch_bounds__(256) k_convA(const float* __restrict__ X)
{
    const int total = B_ * LP * (D_ / 4);
    for (int i = blockIdx.x * blockDim.x + threadIdx.x; i < total;
         i += gridDim.x * blockDim.x) {
        const int m  = i / (D_ / 4);
        const int k4 = i - m * (D_ / 4);
        const int b  = m / LP;
        const int l  = m - b * LP + 1;
        float4 v = *(const float4*)(X + ((size_t)(b * L_ + l)) * D_ + k4 * 4);
        __half2 h01, h23;
        h01.x = __float2half_rn(v.x); h01.y = __float2half_rn(v.y);
        h23.x = __float2half_rn(v.z); h23.y = __float2half_rn(v.w);
        ((__half2*)gA_h)[(size_t)i * 2]     = h01;
        ((__half2*)gA_h)[(size_t)i * 2 + 1] = h23;
    }
}

// =====================================================================
// K0b: W [768,512] -> W^T fp16 [512,768]
// =====================================================================
__global__ void __launch_bounds__(256) k_convW(const float* __restrict__ W)
{
    __shared__ float t[32][33];
    const int nb = blockIdx.x * 32;
    const int kb = blockIdx.y * 32;
    const int tx = threadIdx.x & 31, ty = threadIdx.x >> 5;
#pragma unroll
    for (int r = 0; r < 32; r += 8)
        t[ty + r][tx] = W[(size_t)(kb + ty + r) * HD + nb + tx];
    __syncthreads();
#pragma unroll
    for (int r = 0; r < 32; r += 8)
        gWt_h[(size_t)(nb + ty + r) * D_ + kb + tx] = __float2half_rn(t[tx][ty + r]);
}

// =====================================================================
// K0c: head-weight conversions + out init + zero gSh/gM
// =====================================================================
#define CH_S1 (D_ * NPAD)
#define CH_S2 ((size_t)FPAD * NPAD)
#define CH_S3 (B_ * D_)
#define CH_S4 (B_ * NC)
#define CH_S5 (NH * B_ * DH)         // gSh
#define CH_S6 (NH * B_)              // gM
#define CH_TOTAL (CH_S1 + CH_S2 + CH_S3 + CH_S4 + CH_S5 + CH_S6)

__global__ void __launch_bounds__(256) k_convH(
    const float* __restrict__ w1, const float* __restrict__ w2,
    const float* __restrict__ cls, const float* __restrict__ b1,
    const float* __restrict__ b2, float* __restrict__ out)
{
    for (size_t i = (size_t)blockIdx.x * 256 + threadIdx.x; i < CH_TOTAL;
         i += (size_t)gridDim.x * 256) {
        if (i < CH_S1) {
            const int r = (int)(i >> 10), c = (int)(i & 1023);
            float v = (c < NC) ? w1[(size_t)r * NC + c] : 0.f;
            const __half h = __float2half_rn(v);
            gW1_h[i] = h;
            gW1_l[i] = __float2half_rn(v - __half2float(h));
        } else if (i < CH_S1 + CH_S2) {
            const size_t j = i - CH_S1;
            const int r = (int)(j >> 10), c = (int)(j & 1023);
            float v = (r < FLATN && c < NC) ? w2[(size_t)r * NC + c] : 0.f;
            const __half h = __float2half_rn(v);
            gW2_h[j] = h;
            gW2_l[j] = __float2half_rn(v - __half2float(h));
        } else if (i < CH_S1 + CH_S2 + CH_S3) {
            const size_t j = i - CH_S1 - CH_S2;
            float v = cls[j];
            const __half h = __float2half_rn(v);
            gCls_h[j] = h;
            gCls_l[j] = __float2half_rn(v - __half2float(h));
        } else if (i < CH_S1 + CH_S2 + CH_S3 + CH_S4) {
            const size_t j = i - CH_S1 - CH_S2 - CH_S3;
            const int n = (int)(j % NC);
            out[j] = 0.5f * (b1[n] + b2[n]);
        } else if (i < CH_S1 + CH_S2 + CH_S3 + CH_S4 + CH_S5) {
            gSh[i - CH_S1 - CH_S2 - CH_S3 - CH_S4] = 0.f;
        } else {
            gM[i - CH_S1 - CH_S2 - CH_S3 - CH_S4 - CH_S5] = 0.f;
        }
    }
}

// =====================================================================
// K1: warp-mma fp16 GEMM + FUSED bias + LayerNorm + center-stats
// CTA 128x128, block=128 (4 warps), warp tile 64x64, 2-stage cp.async.
// blockIdx.y == head; N-tile == one head's 128 channels -> LN rows are
// complete inside the CTA. Writes fp16 LN output to gHn_h; accumulates
// fp16 column sums (gSh) + float total (gM) via atomics.   <- ncu probe
// =====================================================================
#define RSB      80
#define TILE_B   (128 * RSB)
#define OFF_AH   0
#define OFF_BH   (1 * TILE_B)
#define STAGE_B  (2 * TILE_B)          // 20480
#define GEMM_SMEM (2 * STAGE_B)        // 40960
#define NCHUNK   (D_ / 32)             // 24

__device__ __forceinline__ void gemm_load_stage(
    uint32_t sb, int buf, int c, int m0, int n0, int tid)
{
    const int k0 = c * 32;
    const uint32_t stg = sb + buf * STAGE_B;
#pragma unroll
    for (int q = 0; q < 4; q++) {
        const int ch  = q * 128 + tid;
        const int row = ch >> 2;
        const int cc  = ch & 3;
        const uint32_t doff = (uint32_t)row * RSB + cc * 16;
        const size_t ga = (size_t)(m0 + row) * D_ + k0 + cc * 8;
        const size_t gb = (size_t)(n0 + row) * D_ + k0 + cc * 8;
        cp16(stg + OFF_AH + doff, gA_h + ga);
        cp16(stg + OFF_BH + doff, gWt_h + gb);
    }
}

__global__ void __launch_bounds__(128, 3) k_gemm_mma(
    const float* __restrict__ bias, const float* __restrict__ lng,
    const float* __restrict__ lnb)
{
    extern __shared__ char smem[];
    __shared__ float rs[128][2];
    __shared__ float rq[128][2];
    const uint32_t sb = smem_u32(smem);
    const int tid  = threadIdx.x;
    const int wid  = tid >> 5;
    const int lane = tid & 31;
    const int wm = wid >> 1;              // 0..1 (m 64 each)
    const int wn = wid & 1;               // 0..1 (n 64 each)
    const int m0 = blockIdx.x * 128;
    const int hh = blockIdx.y;            // head
    const int n0 = hh * 128;

    const uint32_t a_row = (lane & 15);
    const uint32_t a_col = (uint32_t)(lane >> 4) * 16;
    const uint32_t b_row = (lane & 7) + ((lane >> 4) << 3);
    const uint32_t b_col = (uint32_t)((lane >> 3) & 1) * 16;

    uint32_t a_off[4], b_off[4];
#pragma unroll
    for (int mt = 0; mt < 4; mt++)
        a_off[mt] = (uint32_t)(wm * 64 + mt * 16 + a_row) * RSB + a_col;
#pragma unroll
    for (int g = 0; g < 4; g++)
        b_off[g] = (uint32_t)(wn * 64 + g * 16 + b_row) * RSB + b_col;

    float acc[4][8][4];
#pragma unroll
    for (int mt = 0; mt < 4; mt++)
#pragma unroll
        for (int nt = 0; nt < 8; nt++)
#pragma unroll
            for (int e = 0; e < 4; e++) acc[mt][nt][e] = 0.f;

    gemm_load_stage(sb, 0, 0, m0, n0, tid);
    CP_COMMIT();

    for (int c = 0; c < NCHUNK; c++) {
        if (c + 1 < NCHUNK) {
            gemm_load_stage(sb, (c + 1) & 1, c + 1, m0, n0, tid);
            CP_COMMIT();
            CP_WAIT1();
        } else {
            CP_WAIT0();
        }
        __syncthreads();

        const uint32_t stg = sb + (c & 1) * STAGE_B;
#pragma unroll
        for (int ks = 0; ks < 2; ks++) {
            const uint32_t kb = (uint32_t)ks * 32;
            uint32_t ah[4][4];
#pragma unroll
            for (int mt = 0; mt < 4; mt++)
                ldx4(ah[mt], stg + OFF_AH + a_off[mt] + kb);
#pragma unroll
            for (int g = 0; g < 4; g++) {
                uint32_t bh[4];
                ldx4(bh, stg + OFF_BH + b_off[g] + kb);
#pragma unroll
                for (int mt = 0; mt < 4; mt++)
                    mma16816(acc[mt][2 * g],     ah[mt], bh[0], bh[1]);
#pragma unroll
                for (int mt = 0; mt < 4; mt++)
                    mma16816(acc[mt][2 * g + 1], ah[mt], bh[2], bh[3]);
            }
        }
        __syncthreads();
    }

    // ================= fused epilogue: bias + LN + stats =================
    const int gid = lane >> 2;
    const int tig = lane & 3;
    const int b0r   = m0 / LP;
    const int bndry = (b0r + 1) * LP - m0;     // local row where b increments
    const bool has2 = (bndry < 128);

    // per-column constants (d = within-head channel)
    float pb[8][2], gg[8][2], bb[8][2];
#pragma unroll
    for (int nt = 0; nt < 8; nt++) {
        const int d = wn * 64 + nt * 8 + 2 * tig;
        const float2 t0 = *(const float2*)(bias + n0 + d);
        pb[nt][0] = t0.x; pb[nt][1] = t0.y;
        const float2 t1 = *(const float2*)(lng + d);
        gg[nt][0] = t1.x; gg[nt][1] = t1.y;
        const float2 t2 = *(const float2*)(lnb + d);
        bb[nt][0] = t2.x; bb[nt][1] = t2.y;
    }

    // bias add + row sums/sumsq, reduce over tig, stash per-warp halves
#pragma unroll
    for (int mt = 0; mt < 4; mt++) {
        float sA = 0.f, qA = 0.f, sB = 0.f, qB = 0.f;
#pragma unroll
        for (int nt = 0; nt < 8; nt++) {
#pragma unroll
            for (int e = 0; e < 2; e++) {
                const float vA = acc[mt][nt][e]     + pb[nt][e];
                const float vB = acc[mt][nt][2 + e] + pb[nt][e];
                acc[mt][nt][e] = vA; acc[mt][nt][2 + e] = vB;
                sA += vA; qA += vA * vA;
                sB += vB; qB += vB * vB;
            }
        }
        sA += __shfl_xor_sync(0xffffffffu, sA, 1);
        sA += __shfl_xor_sync(0xffffffffu, sA, 2);
        qA += __shfl_xor_sync(0xffffffffu, qA, 1);
        qA += __shfl_xor_sync(0xffffffffu, qA, 2);
        sB += __shfl_xor_sync(0xffffffffu, sB, 1);
        sB += __shfl_xor_sync(0xffffffffu, sB, 2);
        qB += __shfl_xor_sync(0xffffffffu, qB, 1);
        qB += __shfl_xor_sync(0xffffffffu, qB, 2);
        if (tig == 0) {
            const int rA = wm * 64 + mt * 16 + gid;
            rs[rA][wn] = sA;     rq[rA][wn] = qA;
            rs[rA + 8][wn] = sB; rq[rA + 8][wn] = qB;
        }
    }
    __syncthreads();

    float colp[2][16];
#pragma unroll
    for (int s = 0; s < 2; s++)
#pragma unroll
        for (int j = 0; j < 16; j++) colp[s][j] = 0.f;
    float fs0 = 0.f, fs1 = 0.f;

#pragma unroll
    for (int mt = 0; mt < 4; mt++) {
#pragma unroll
        for (int half = 0; half < 2; half++) {
            const int lr = wm * 64 + mt * 16 + half * 8 + gid;
            const float mu   = (rs[lr][0] + rs[lr][1]) * (1.0f / 128.0f);
            const float var  = (rq[lr][0] + rq[lr][1]) * (1.0f / 128.0f) - mu * mu;
            const float rstd = rsqrtf(var + 1e-5f);
            const int seg = (lr >= bndry) ? 1 : 0;
            const int bg  = b0r + seg;
            const int lrw = (m0 + lr) - bg * LP;
            __half* dst = gHn_h + ((size_t)(hh * B_ + bg) * LP + lrw) * DH;
            float fsl = 0.f;
#pragma unroll
            for (int nt = 0; nt < 8; nt++) {
                const float o0 = (acc[mt][nt][half * 2 + 0] - mu) * rstd * gg[nt][0] + bb[nt][0];
                const float o1 = (acc[mt][nt][half * 2 + 1] - mu) * rstd * gg[nt][1] + bb[nt][1];
                __half2 hv;
                hv.x = __float2half_rn(o0);
                hv.y = __float2half_rn(o1);
                *(__half2*)(dst + wn * 64 + nt * 8 + 2 * tig) = hv;
                colp[seg][nt * 2 + 0] += __half2float(hv.x);
                colp[seg][nt * 2 + 1] += __half2float(hv.y);
                fsl += o0 + o1;
            }
            if (seg) fs1 += fsl; else fs0 += fsl;
        }
    }

    // reduce column partials over gid lanes (bits 4,8,16)
#pragma unroll
    for (int s = 0; s < 2; s++)
#pragma unroll
        for (int j = 0; j < 16; j++) {
            colp[s][j] += __shfl_xor_sync(0xffffffffu, colp[s][j], 4);
            colp[s][j] += __shfl_xor_sync(0xffffffffu, colp[s][j], 8);
            colp[s][j] += __shfl_xor_sync(0xffffffffu, colp[s][j], 16);
        }
#pragma unroll
    for (int o = 1; o <= 16; o <<= 1) {
        fs0 += __shfl_xor_sync(0xffffffffu, fs0, o);
        fs1 += __shfl_xor_sync(0xffffffffu, fs1, o);
    }
    if (lane == 0) {
        atomicAdd(&gM[hh * B_ + b0r], fs0);
        if (has2) atomicAdd(&gM[hh * B_ + b0r + 1], fs1);
    }
    if (gid == 0) {
#pragma unroll
        for (int nt = 0; nt < 8; nt++) {
            const int d0 = wn * 64 + nt * 8 + 2 * tig;
            atomicAdd(&gSh[(size_t)(hh * B_ + b0r) * DH + d0],     colp[0][nt * 2 + 0]);
            atomicAdd(&gSh[(size_t)(hh * B_ + b0r) * DH + d0 + 1], colp[0][nt * 2 + 1]);
            if (has2) {
                atomicAdd(&gSh[(size_t)(hh * B_ + b0r + 1) * DH + d0],     colp[1][nt * 2 + 0]);
                atomicAdd(&gSh[(size_t)(hh * B_ + b0r + 1) * DH + d0 + 1], colp[1][nt * 2 + 1]);
            }
        }
    }
}

// =====================================================================
// K3: cov via fp16 mma single-pass, trans-ldmatrix, rank-1 centering
// =====================================================================
#define CRS2   136
#define CRSB2  (CRS2 * 2)               // 272 B
#define CTILE2 (208 * CRSB2)            // 56576
#define COV_SMEM (2 * CTILE2)           // 113,152

__global__ void __launch_bounds__(256) k_cov_mma()
{
    extern __shared__ char csm[];
    const uint32_t sb = smem_u32(csm);
    __shared__ float colsq[DH];
    __shared__ float s1s[DH];
    __shared__ float s2s[DH];

    const int p = blockIdx.x;
    const int b = blockIdx.y;
    const int tid  = threadIdx.x;
    const int wid  = tid >> 5;
    const int lane = tid & 31;
    const int wm = wid >> 1;
    const int wn = wid & 1;

    const __half* Asrc = gHn_h + ((size_t)(p * B_ + b)) * LP * DH;
    const __half* Bhs  = gHn_h + ((size_t)((p + 1) * B_ + b)) * LP * DH;

    const uint32_t tA = sb, tBh = sb + CTILE2;

    for (int i = tid; i < 2 * 12 * 17; i += 256) {
        const int tile = i / 204;
        const int rem  = i % 204;
        const int r    = rem / 17;
        const int c    = rem % 17;
        *(uint4*)(csm + (size_t)tile * CTILE2 + (196 + r) * CRSB2 + c * 16) =
            make_uint4(0u, 0u, 0u, 0u);
    }
    for (int t = tid; t < LP * 16; t += 256) {
        const int row = t >> 4;
        const int ch  = t & 15;
        const uint32_t doff = (uint32_t)row * CRSB2 + ch * 16;
        const size_t   goff = (size_t)row * DH + ch * 8;
        cp16(tA  + doff, Asrc + goff);
        cp16(tBh + doff, Bhs + goff);
    }
    CP_COMMIT();
    if (tid < DH) {
        colsq[tid] = 0.f;
        s1s[tid] = gSh[(size_t)(p * B_ + b) * DH + tid];
        s2s[tid] = gSh[(size_t)((p + 1) * B_ + b) * DH + tid];
    }
    CP_WAIT0();
    __syncthreads();

    const uint32_t ar = (lane & 7) + ((lane >> 4) << 3);
    const uint32_t ac = ((lane >> 3) & 1) * 16;
    const uint32_t br = (lane & 7) + (((lane >> 3) & 1) << 3);
    const uint32_t bc = (uint32_t)(lane >> 4) * 16;

    uint32_t a_off[2], b_off[4];
#pragma unroll
    for (int mt = 0; mt < 2; mt++)
        a_off[mt] = ar * CRSB2 + (uint32_t)(wm * 32 + mt * 16) * 2 + ac;
#pragma unroll
    for (int g = 0; g < 4; g++)
        b_off[g] = br * CRSB2 + (uint32_t)(wn * 64 + g * 16) * 2 + bc;

    float acc[2][8][4];
#pragma unroll
    for (int mt = 0; mt < 2; mt++)
#pragma unroll
        for (int nt = 0; nt < 8; nt++)
#pragma unroll
            for (int e = 0; e < 4; e++) acc[mt][nt][e] = 0.f;

#pragma unroll
    for (int ks = 0; ks < 13; ks++) {
        const uint32_t kb = (uint32_t)ks * 16 * CRSB2;
        uint32_t ah[2][4];
#pragma unroll
        for (int mt = 0; mt < 2; mt++)
            ldx4t(ah[mt], tA + a_off[mt] + kb);
#pragma unroll
        for (int g = 0; g < 4; g++) {
            uint32_t bh[4];
            ldx4t(bh, tBh + b_off[g] + kb);
#pragma unroll
            for (int mt = 0; mt < 2; mt++) {
                mma16816(acc[mt][2 * g],     ah[mt], bh[0], bh[1]);
                mma16816(acc[mt][2 * g + 1], ah[mt], bh[2], bh[3]);
            }
        }
    }

    const float m1 = gM[p * B_ + b] * (1.0f / (LP * DH));
    const float m2 = gM[(p + 1) * B_ + b] * (1.0f / (LP * DH));
    const float c12 = (float)LP * m1 * m2;
    const int gid = lane >> 2;
    const int tig = lane & 3;
#pragma unroll
    for (int mt = 0; mt < 2; mt++) {
        const int d0 = wm * 32 + mt * 16 + gid;
        const float t1a = m2 * s1s[d0]     - c12;
        const float t1b = m2 * s1s[d0 + 8] - c12;
#pragma unroll
        for (int nt = 0; nt < 8; nt++) {
            const int e0 = wn * 64 + nt * 8 + 2 * tig;
            const float t2a = m1 * s2s[e0];
            const float t2b = m1 * s2s[e0 + 1];
            acc[mt][nt][0] -= t1a + t2a;
            acc[mt][nt][1] -= t1a + t2b;
            acc[mt][nt][2] -= t1b + t2a;
            acc[mt][nt][3] -= t1b + t2b;
        }
    }

#pragma unroll
    for (int nt = 0; nt < 8; nt++) {
        float s0 = acc[0][nt][0] * acc[0][nt][0] + acc[0][nt][2] * acc[0][nt][2]
                 + acc[1][nt][0] * acc[1][nt][0] + acc[1][nt][2] * acc[1][nt][2];
        float s1 = acc[0][nt][1] * acc[0][nt][1] + acc[0][nt][3] * acc[0][nt][3]
                 + acc[1][nt][1] * acc[1][nt][1] + acc[1][nt][3] * acc[1][nt][3];
#pragma unroll
        for (int o = 4; o <= 16; o <<= 1) {
            s0 += __shfl_xor_sync(0xffffffffu, s0, o);
            s1 += __shfl_xor_sync(0xffffffffu, s1, o);
        }
        if (lane < 4) {
            const int col = wn * 64 + nt * 8 + 2 * lane;
            atomicAdd(&colsq[col], s0);
            atomicAdd(&colsq[col + 1], s1);
        }
    }
    __syncthreads();

    float* outb = g_cov + ((size_t)(b * 3 + p)) * (DH * DH);
#pragma unroll
    for (int nt = 0; nt < 8; nt++) {
        const int col = wn * 64 + nt * 8 + 2 * tig;
        const float i0 = 1.0f / fmaxf(sqrtf(colsq[col]),     (float)LP * 1e-12f);
        const float i1 = 1.0f / fmaxf(sqrtf(colsq[col + 1]), (float)LP * 1e-12f);
#pragma unroll
        for (int mt = 0; mt < 2; mt++) {
            const int r0 = wm * 32 + mt * 16 + gid;
            float2 v0 = make_float2(acc[mt][nt][0] * i0, acc[mt][nt][1] * i1);
            float2 v1 = make_float2(acc[mt][nt][2] * i0, acc[mt][nt][3] * i1);
            *(float2*)(outb + (size_t)r0 * DH + col)       = v0;
            *(float2*)(outb + (size_t)(r0 + 8) * DH + col) = v1;
        }
    }
}

// =====================================================================
// K4: fused conv1 -> GELU -> conv2 ; emits flat as fp16 hi/lo (padded)
// =====================================================================
#define CONV_CS_B  (3 * 66 * 128 * 4)
#define CONV_SMEM  (CONV_CS_B + 3 * 3969 * 4)  // 149,004

__global__ void __launch_bounds__(256) k_conv(
    const float* __restrict__ w1, const float* __restrict__ w2)
{
    extern __shared__ char cvsm[];
    float* cs = (float*)cvsm;
    float* z1 = (float*)(cvsm + CONV_CS_B);
    __shared__ float w1s[81];
    __shared__ float w2s[81];

    const int b = blockIdx.x;
    const int tid = threadIdx.x;
    if (tid < 81) { w1s[tid] = w1[tid]; w2s[tid] = w2[tid]; }

    const float* cb = g_cov + (size_t)b * 3 * DH * DH;

#pragma unroll 1
    for (int ph = 0; ph < 2; ph++) {
        const int r0 = ph * 64;
        const int nr = ph ? 64 : 66;
        const int y0 = ph ? 32 : 0;
        const int ny = ph ? 31 : 32;
        __syncthreads();
        for (int i = tid; i < 3 * nr * 32; i += 256) {
            const int c  = i / (nr * 32);
            const int rr = (i / 32) % nr;
            const int q  = i % 32;
            *(float4*)(cs + (c * 66 + rr) * 128 + q * 4) =
                *(const float4*)(cb + (size_t)c * (DH * DH) + (r0 + rr) * DH + q * 4);
        }
        __syncthreads();
        for (int idx = tid; idx < 3 * ny * 63; idx += 256) {
            const int c = idx / (ny * 63);
            const int r = idx % (ny * 63);
            const int y = y0 + r / 63;
            const int x = r % 63;
            float s = 0.f;
#pragma unroll
            for (int ci = 0; ci < 3; ci++)
#pragma unroll
                for (int ky = 0; ky < 3; ky++)
#pragma unroll
                    for (int kx = 0; kx < 3; kx++)
                        s += cs[(ci * 66 + (2 * y + ky - r0)) * 128 + 2 * x + kx]
                           * w1s[((c * 3 + ci) * 3 + ky) * 3 + kx];
            s = 0.5f * s * (1.0f + erff(s * 0.70710678118654752f));
            z1[c * 3969 + y * 63 + x] = s;
        }
    }
    __syncthreads();

    __half* fh = gF_h + (size_t)b * FPAD;
    __half* fl = gF_l + (size_t)b * FPAD;
    for (int idx = tid; idx < FLATN; idx += 256) {
        const int c = idx / 961;
        const int r = idx % 961;
        const int y = r / 31, x = r % 31;
        float s = 0.f;
#pragma unroll
        for (int ci = 0; ci < 3; ci++)
#pragma unroll
            for (int ky = 0; ky < 3; ky++)
#pragma unroll
                for (int kx = 0; kx < 3; kx++)
                    s += z1[ci * 3969 + (2 * y + ky) * 63 + (2 * x + kx)]
                       * w2s[((c * 3 + ci) * 3 + ky) * 3 + kx];
        const __half hv = __float2half_rn(s);
        fh[idx] = hv;
        fl[idx] = __float2half_rn(s - __half2float(hv));
    }
    for (int idx = FLATN + tid; idx < FPAD; idx += 256) {
        fh[idx] = __float2half_rn(0.f);
        fl[idx] = __float2half_rn(0.f);
    }
}

// =====================================================================
// K5: classifier head via fp16 mma, 3-pass split, k-split=4 + atomicAdd
// =====================================================================
#define HRSB   80
#define HBRS   272
#define OFF_AH2 0
#define OFF_AL2 (64 * HRSB)
#define OFF_BH2 (2 * 64 * HRSB)
#define OFF_BL2 (OFF_BH2 + 32 * HBRS)
#define HSTAGE  (OFF_BL2 + 32 * HBRS)   // 27648
#define HEAD_SMEM (2 * HSTAGE)          // 55296

__device__ __forceinline__ void head_load_stage(
    uint32_t sb, int buf, int chunk, int m0, int n0, int tid)
{
    const uint32_t stg = sb + buf * HSTAGE;
    const bool in_cls = (chunk < HK_CLS_CHUNKS);
    const int  kr     = in_cls ? chunk * 32 : (chunk - HK_CLS_CHUNKS) * 32;
    const __half* Ah = in_cls ? gCls_h : gF_h;
    const __half* Al = in_cls ? gCls_l : gF_l;
    const __half* Bh = in_cls ? gW1_h  : gW2_h;
    const __half* Bl = in_cls ? gW1_l  : gW2_l;
    const int astr = in_cls ? D_ : FPAD;

    {
        const int idx = tid;
        const int row = idx >> 2;
        const int q   = idx & 3;
        const uint32_t doff = (uint32_t)row * HRSB + q * 16;
        const size_t goff = (size_t)(m0 + row) * astr + kr + q * 8;
        cp16(stg + OFF_AH2 + doff, Ah + goff);
        cp16(stg + OFF_AL2 + doff, Al + goff);
    }
#pragma unroll
    for (int j = 0; j < 2; j++) {
        const int idx = j * 256 + tid;
        const int row = idx >> 4;
        const int q   = idx & 15;
        const uint32_t doff = (uint32_t)row * HBRS + q * 16;
        const size_t goff = (size_t)(kr + row) * NPAD + n0 + q * 8;
        cp16(stg + OFF_BH2 + doff, Bh + goff);
        cp16(stg + OFF_BL2 + doff, Bl + goff);
    }
}

__global__ void __launch_bounds__(256) k_head_mma(float* __restrict__ out)
{
    extern __shared__ char hsm[];
    const uint32_t sb = smem_u32(hsm);
    const int tid  = threadIdx.x;
    const int wid  = tid >> 5;
    const int lane = tid & 31;
    const int wm = wid >> 2;
    const int wn = wid & 3;
    const int m0 = blockIdx.x * 64;
    const int n0 = blockIdx.y * 128;
    const int c0 = blockIdx.z * HK_SPLIT;

    const uint32_t a_row = (lane & 15);
    const uint32_t a_col = (uint32_t)(lane >> 4) * 16;
    const uint32_t br = (lane & 7) + (((lane >> 3) & 1) << 3);
    const uint32_t bc = (uint32_t)(lane >> 4) * 16;

    uint32_t a_off[2], b_off[2];
#pragma unroll
    for (int mt = 0; mt < 2; mt++)
        a_off[mt] = (uint32_t)(wm * 32 + mt * 16 + a_row) * HRSB + a_col;
#pragma unroll
    for (int g = 0; g < 2; g++)
        b_off[g] = br * HBRS + (uint32_t)(wn * 32 + g * 16) * 2 + bc;

    float acc[2][4][4];
#pragma unroll
    for (int mt = 0; mt < 2; mt++)
#pragma unroll
        for (int nf = 0; nf < 4; nf++)
#pragma unroll
            for (int e = 0; e < 4; e++) acc[mt][nf][e] = 0.f;

    head_load_stage(sb, 0, c0, m0, n0, tid);
    CP_COMMIT();

    for (int i = 0; i < HK_SPLIT; i++) {
        if (i + 1 < HK_SPLIT) {
            head_load_stage(sb, (i + 1) & 1, c0 + i + 1, m0, n0, tid);
            CP_COMMIT();
            CP_WAIT1();
        } else {
            CP_WAIT0();
        }
        __syncthreads();

        const uint32_t stg = sb + (i & 1) * HSTAGE;
#pragma unroll
        for (int ks = 0; ks < 2; ks++) {
            uint32_t ah[2][4], al[2][4];
#pragma unroll
            for (int mt = 0; mt < 2; mt++) {
                ldx4(ah[mt], stg + OFF_AH2 + a_off[mt] + ks * 32);
                ldx4(al[mt], stg + OFF_AL2 + a_off[mt] + ks * 32);
            }
            const uint32_t kbb = (uint32_t)ks * 16 * HBRS;
#pragma unroll
            for (int g = 0; g < 2; g++) {
                uint32_t bh[4], bl[4];
                ldx4t(bh, stg + OFF_BH2 + b_off[g] + kbb);
                ldx4t(bl, stg + OFF_BL2 + b_off[g] + kbb);
#pragma unroll
                for (int mt = 0; mt < 2; mt++) {
                    mma16816(acc[mt][2 * g],     ah[mt], bh[0], bh[1]);
                    mma16816(acc[mt][2 * g],     ah[mt], bl[0], bl[1]);
                    mma16816(acc[mt][2 * g],     al[mt], bh[0], bh[1]);
                    mma16816(acc[mt][2 * g + 1], ah[mt], bh[2], bh[3]);
                    mma16816(acc[mt][2 * g + 1], ah[mt], bl[2], bl[3]);
                    mma16816(acc[mt][2 * g + 1], al[mt], bh[2], bh[3]);
                }
            }
        }
        __syncthreads();
    }

    const int gid = lane >> 2;
    const int tig = lane & 3;
#pragma unroll
    for (int mt = 0; mt < 2; mt++) {
        const int r0 = m0 + wm * 32 + mt * 16 + gid;
#pragma unroll
        for (int nf = 0; nf < 4; nf++) {
            const int col = n0 + wn * 32 + nf * 8 + 2 * tig;
            if (col < NC) {
                atomicAdd(out + (size_t)r0 * NC + col,       0.5f * acc[mt][nf][0]);
                atomicAdd(out + (size_t)r0 * NC + col + 1,   0.5f * acc[mt][nf][1]);
                atomicAdd(out + (size_t)(r0 + 8) * NC + col,     0.5f * acc[mt][nf][2]);
                atomicAdd(out + (size_t)(r0 + 8) * NC + col + 1, 0.5f * acc[mt][nf][3]);
            }
        }
    }
}

// =====================================================================
// launch
// =====================================================================
extern "C" void kernel_launch(void* const* d_in, const int* in_sizes, int n_in,
                              void* d_out, int out_size)
{
    const float* cls_token = (const float*)d_in[0];
    const float* x         = (const float*)d_in[1];
    const float* proj_w    = (const float*)d_in[2];
    const float* proj_b    = (const float*)d_in[3];
    const float* ln_g      = (const float*)d_in[4];
    const float* ln_b      = (const float*)d_in[5];
    const float* conv1_w   = (const float*)d_in[6];
    const float* conv2_w   = (const float*)d_in[7];
    const float* cls1_w    = (const float*)d_in[8];
    const float* cls1_b    = (const float*)d_in[9];
    const float* cls2_w    = (const float*)d_in[10];
    const float* cls2_b    = (const float*)d_in[11];
    float* out = (float*)d_out;

    cudaFuncSetAttribute(k_gemm_mma,
                         cudaFuncAttributeMaxDynamicSharedMemorySize, GEMM_SMEM);
    cudaFuncSetAttribute(k_cov_mma,
                         cudaFuncAttributeMaxDynamicSharedMemorySize, COV_SMEM);
    cudaFuncSetAttribute(k_conv,
                         cudaFuncAttributeMaxDynamicSharedMemorySize, CONV_SMEM);
    cudaFuncSetAttribute(k_head_mma,
                         cudaFuncAttributeMaxDynamicSharedMemorySize, HEAD_SMEM);

    k_convA<<<2048, 256>>>(x);                                      // 0
    k_convW<<<dim3(HD / 32, D_ / 32), 256>>>(proj_w);               // 1
    k_convH<<<2048, 256>>>(cls1_w, cls2_w, cls_token,
                           cls1_b, cls2_b, out);                    // 2
    k_gemm_mma<<<dim3(392, 4), 128, GEMM_SMEM>>>(proj_b, ln_g, ln_b); // 3 <- ncu probe
    k_cov_mma<<<dim3(3, B_), 256, COV_SMEM>>>();                    // 4
    k_conv<<<B_, 256, CONV_SMEM>>>(conv1_w, conv2_w);               // 5
    k_head_mma<<<dim3(4, 8, 4), 256, HEAD_SMEM>>>(out);             // 6
}

// round 17
// speedup vs baseline: 1.1509x; 1.0131x over previous
#include <cuda_runtime.h>
#include <cuda_bf16.h>
#include <cuda_fp16.h>
#include <math.h>
#include <stdint.h>

// ---------------- problem constants ----------------
#define B_    256
#define L_    197
#define LP    196
#define D_    768
#define HD    512
#define DH    128
#define NH    4
#define NC    1000
#define FLATN 2883   // 3*31*31
#define FPAD  2944   // flat padded to multiple of 32
#define NPAD  1024   // classifier N padded
#define HK_CLS_CHUNKS  24          // 768/32
#define HK_CHUNKS      116         // 24 + 92
#define HK_SPLIT       29          // chunks per k-split (116/4)

// ---------------- scratch (static __device__, no allocation) ----------------
__device__ float g_cov[(size_t)B_ * 3 * DH * DH];     // (b,p,d,e) NCHW

// fp16 buffers for tensor-core projection GEMM (single-pass: hi only)
__device__ __half gA_h[(size_t)B_ * LP * D_];    // [50176,768]
__device__ __half gWt_h[(size_t)HD * D_];        // [512,768]  W^T

// LN output (UNcentered) fp16, natural layout (h,b, l=196, d=128)
__device__ __half gHn_h[(size_t)NH * B_ * LP * DH];

// classifier-head fp16 buffers (3-pass: hi+lo kept for accuracy)
__device__ __half gW1_h[(size_t)D_ * NPAD];      // [768,1024]
__device__ __half gW1_l[(size_t)D_ * NPAD];
__device__ __half gW2_h[(size_t)FPAD * NPAD];    // [2944,1024]
__device__ __half gW2_l[(size_t)FPAD * NPAD];
__device__ __half gCls_h[(size_t)B_ * D_];       // [256,768]
__device__ __half gCls_l[(size_t)B_ * D_];
__device__ __half gF_h[(size_t)B_ * FPAD];       // [256,2944]
__device__ __half gF_l[(size_t)B_ * FPAD];

// ---------------- baseline-PTX helpers ----------------
__device__ __forceinline__ uint32_t smem_u32(const void* p) {
    uint32_t a;
    asm("{ .reg .u64 t; cvta.to.shared.u64 t, %1; cvt.u32.u64 %0, t; }"
        : "=r"(a) : "l"(p));
    return a;
}
__device__ __forceinline__ void cp16(uint32_t dst, const void* src) {
    asm volatile("cp.async.ca.shared.global [%0], [%1], 16;"
                 :: "r"(dst), "l"(src) : "memory");
}
#define CP_COMMIT() asm volatile("cp.async.commit_group;" ::: "memory")
#define CP_WAIT0()  asm volatile("cp.async.wait_group 0;" ::: "memory")
#define CP_WAIT1()  asm volatile("cp.async.wait_group 1;" ::: "memory")

__device__ __forceinline__ void ldx4(uint32_t* r, uint32_t addr) {
    asm volatile("ldmatrix.sync.aligned.m8n8.x4.shared.b16 {%0,%1,%2,%3}, [%4];"
                 : "=r"(r[0]), "=r"(r[1]), "=r"(r[2]), "=r"(r[3]) : "r"(addr));
}
__device__ __forceinline__ void ldx4t(uint32_t* r, uint32_t addr) {
    asm volatile("ldmatrix.sync.aligned.m8n8.x4.trans.shared.b16 {%0,%1,%2,%3}, [%4];"
                 : "=r"(r[0]), "=r"(r[1]), "=r"(r[2]), "=r"(r[3]) : "r"(addr));
}
__device__ __forceinline__ void mma16816(float* c, const uint32_t* a,
                                         uint32_t b0, uint32_t b1) {
    asm volatile(
        "mma.sync.aligned.m16n8k16.row.col.f32.f16.f16.f32 "
        "{%0,%1,%2,%3}, {%4,%5,%6,%7}, {%8,%9}, {%0,%1,%2,%3};"
        : "+f"(c[0]), "+f"(c[1]), "+f"(c[2]), "+f"(c[3])
        : "r"(a[0]), "r"(a[1]), "r"(a[2]), "r"(a[3]), "r"(b0), "r"(b1));
}

// =====================================================================
// K0a: round x[:,1:,:] to fp16  [50176,768]
// =====================================================================
__global__ void __launch_bounds__(256) k_convA(const float* __restrict__ X)
{
    const int total = B_ * LP * (D_ / 4);
    for (int i = blockIdx.x * blockDim.x + threadIdx.x; i < total;
         i += gridDim.x * blockDim.x) {
        const int m  = i / (D_ / 4);
        const int k4 = i - m * (D_ / 4);
        const int b  = m / LP;
        const int l  = m - b * LP + 1;
        float4 v = *(const float4*)(X + ((size_t)(b * L_ + l)) * D_ + k4 * 4);
        __half2 h01, h23;
        h01.x = __float2half_rn(v.x); h01.y = __float2half_rn(v.y);
        h23.x = __float2half_rn(v.z); h23.y = __float2half_rn(v.w);
        ((__half2*)gA_h)[(size_t)i * 2]     = h01;
        ((__half2*)gA_h)[(size_t)i * 2 + 1] = h23;
    }
}

// =====================================================================
// K0b: W [768,512] -> W^T fp16 [512,768]
// =====================================================================
__global__ void __launch_bounds__(256) k_convW(const float* __restrict__ W)
{
    __shared__ float t[32][33];
    const int nb = blockIdx.x * 32;
    const int kb = blockIdx.y * 32;
    const int tx = threadIdx.x & 31, ty = threadIdx.x >> 5;
#pragma unroll
    for (int r = 0; r < 32; r += 8)
        t[ty + r][tx] = W[(size_t)(kb + ty + r) * HD + nb + tx];
    __syncthreads();
#pragma unroll
    for (int r = 0; r < 32; r += 8)
        gWt_h[(size_t)(nb + ty + r) * D_ + kb + tx] = __float2half_rn(t[tx][ty + r]);
}

// =====================================================================
// K0c: head-weight conversions + out init
// =====================================================================
#define CH_S1 (D_ * NPAD)
#define CH_S2 ((size_t)FPAD * NPAD)
#define CH_S3 (B_ * D_)
#define CH_S4 (B_ * NC)
#define CH_TOTAL (CH_S1 + CH_S2 + CH_S3 + CH_S4)

__global__ void __launch_bounds__(256) k_convH(
    const float* __restrict__ w1, const float* __restrict__ w2,
    const float* __restrict__ cls, const float* __restrict__ b1,
    const float* __restrict__ b2, float* __restrict__ out)
{
    for (size_t i = (size_t)blockIdx.x * 256 + threadIdx.x; i < CH_TOTAL;
         i += (size_t)gridDim.x * 256) {
        if (i < CH_S1) {
            const int r = (int)(i >> 10), c = (int)(i & 1023);
            float v = (c < NC) ? w1[(size_t)r * NC + c] : 0.f;
            const __half h = __float2half_rn(v);
            gW1_h[i] = h;
            gW1_l[i] = __float2half_rn(v - __half2float(h));
        } else if (i < CH_S1 + CH_S2) {
            const size_t j = i - CH_S1;
            const int r = (int)(j >> 10), c = (int)(j & 1023);
            float v = (r < FLATN && c < NC) ? w2[(size_t)r * NC + c] : 0.f;
            const __half h = __float2half_rn(v);
            gW2_h[j] = h;
            gW2_l[j] = __float2half_rn(v - __half2float(h));
        } else if (i < CH_S1 + CH_S2 + CH_S3) {
            const size_t j = i - CH_S1 - CH_S2;
            float v = cls[j];
            const __half h = __float2half_rn(v);
            gCls_h[j] = h;
            gCls_l[j] = __float2half_rn(v - __half2float(h));
        } else {
            const size_t j = i - CH_S1 - CH_S2 - CH_S3;
            const int n = (int)(j % NC);
            out[j] = 0.5f * (b1[n] + b2[n]);
        }
    }
}

// =====================================================================
// K1: warp-mma fp16 GEMM + FUSED bias + LayerNorm (stats moved to cov)
// CTA 128x128, block=128 (4 warps), warp tile 64x64, 2-stage cp.async.
// blockIdx.y == head; writes fp16 LN output straight to gHn_h.
// =====================================================================
#define RSB      80
#define TILE_B   (128 * RSB)
#define OFF_AH   0
#define OFF_BH   (1 * TILE_B)
#define STAGE_B  (2 * TILE_B)          // 20480
#define GEMM_SMEM (2 * STAGE_B)        // 40960
#define NCHUNK   (D_ / 32)             // 24

__device__ __forceinline__ void gemm_load_stage(
    uint32_t sb, int buf, int c, int m0, int n0, int tid)
{
    const int k0 = c * 32;
    const uint32_t stg = sb + buf * STAGE_B;
#pragma unroll
    for (int q = 0; q < 4; q++) {
        const int ch  = q * 128 + tid;
        const int row = ch >> 2;
        const int cc  = ch & 3;
        const uint32_t doff = (uint32_t)row * RSB + cc * 16;
        const size_t ga = (size_t)(m0 + row) * D_ + k0 + cc * 8;
        const size_t gb = (size_t)(n0 + row) * D_ + k0 + cc * 8;
        cp16(stg + OFF_AH + doff, gA_h + ga);
        cp16(stg + OFF_BH + doff, gWt_h + gb);
    }
}

__global__ void __launch_bounds__(128, 3) k_gemm_mma(
    const float* __restrict__ bias, const float* __restrict__ lng,
    const float* __restrict__ lnb)
{
    extern __shared__ char smem[];
    __shared__ float rs[128][2];
    __shared__ float rq[128][2];
    const uint32_t sb = smem_u32(smem);
    const int tid  = threadIdx.x;
    const int wid  = tid >> 5;
    const int lane = tid & 31;
    const int wm = wid >> 1;
    const int wn = wid & 1;
    const int m0 = blockIdx.x * 128;
    const int hh = blockIdx.y;
    const int n0 = hh * 128;

    const uint32_t a_row = (lane & 15);
    const uint32_t a_col = (uint32_t)(lane >> 4) * 16;
    const uint32_t b_row = (lane & 7) + ((lane >> 4) << 3);
    const uint32_t b_col = (uint32_t)((lane >> 3) & 1) * 16;

    uint32_t a_off[4], b_off[4];
#pragma unroll
    for (int mt = 0; mt < 4; mt++)
        a_off[mt] = (uint32_t)(wm * 64 + mt * 16 + a_row) * RSB + a_col;
#pragma unroll
    for (int g = 0; g < 4; g++)
        b_off[g] = (uint32_t)(wn * 64 + g * 16 + b_row) * RSB + b_col;

    float acc[4][8][4];
#pragma unroll
    for (int mt = 0; mt < 4; mt++)
#pragma unroll
        for (int nt = 0; nt < 8; nt++)
#pragma unroll
            for (int e = 0; e < 4; e++) acc[mt][nt][e] = 0.f;

    gemm_load_stage(sb, 0, 0, m0, n0, tid);
    CP_COMMIT();

    for (int c = 0; c < NCHUNK; c++) {
        if (c + 1 < NCHUNK) {
            gemm_load_stage(sb, (c + 1) & 1, c + 1, m0, n0, tid);
            CP_COMMIT();
            CP_WAIT1();
        } else {
            CP_WAIT0();
        }
        __syncthreads();

        const uint32_t stg = sb + (c & 1) * STAGE_B;
#pragma unroll
        for (int ks = 0; ks < 2; ks++) {
            const uint32_t kb = (uint32_t)ks * 32;
            uint32_t ah[4][4];
#pragma unroll
            for (int mt = 0; mt < 4; mt++)
                ldx4(ah[mt], stg + OFF_AH + a_off[mt] + kb);
#pragma unroll
            for (int g = 0; g < 4; g++) {
                uint32_t bh[4];
                ldx4(bh, stg + OFF_BH + b_off[g] + kb);
#pragma unroll
                for (int mt = 0; mt < 4; mt++)
                    mma16816(acc[mt][2 * g],     ah[mt], bh[0], bh[1]);
#pragma unroll
                for (int mt = 0; mt < 4; mt++)
                    mma16816(acc[mt][2 * g + 1], ah[mt], bh[2], bh[3]);
            }
        }
        __syncthreads();
    }

    // ============ fused epilogue: bias + LayerNorm + store ============
    const int gid = lane >> 2;
    const int tig = lane & 3;
    const int b0r   = m0 / LP;
    const int bndry = (b0r + 1) * LP - m0;

    float pb[8][2], gg[8][2], bb[8][2];
#pragma unroll
    for (int nt = 0; nt < 8; nt++) {
        const int d = wn * 64 + nt * 8 + 2 * tig;
        const float2 t0 = *(const float2*)(bias + n0 + d);
        pb[nt][0] = t0.x; pb[nt][1] = t0.y;
        const float2 t1 = *(const float2*)(lng + d);
        gg[nt][0] = t1.x; gg[nt][1] = t1.y;
        const float2 t2 = *(const float2*)(lnb + d);
        bb[nt][0] = t2.x; bb[nt][1] = t2.y;
    }

#pragma unroll
    for (int mt = 0; mt < 4; mt++) {
        float sA = 0.f, qA = 0.f, sB = 0.f, qB = 0.f;
#pragma unroll
        for (int nt = 0; nt < 8; nt++) {
#pragma unroll
            for (int e = 0; e < 2; e++) {
                const float vA = acc[mt][nt][e]     + pb[nt][e];
                const float vB = acc[mt][nt][2 + e] + pb[nt][e];
                acc[mt][nt][e] = vA; acc[mt][nt][2 + e] = vB;
                sA += vA; qA += vA * vA;
                sB += vB; qB += vB * vB;
            }
        }
        sA += __shfl_xor_sync(0xffffffffu, sA, 1);
        sA += __shfl_xor_sync(0xffffffffu, sA, 2);
        qA += __shfl_xor_sync(0xffffffffu, qA, 1);
        qA += __shfl_xor_sync(0xffffffffu, qA, 2);
        sB += __shfl_xor_sync(0xffffffffu, sB, 1);
        sB += __shfl_xor_sync(0xffffffffu, sB, 2);
        qB += __shfl_xor_sync(0xffffffffu, qB, 1);
        qB += __shfl_xor_sync(0xffffffffu, qB, 2);
        if (tig == 0) {
            const int rA = wm * 64 + mt * 16 + gid;
            rs[rA][wn] = sA;     rq[rA][wn] = qA;
            rs[rA + 8][wn] = sB; rq[rA + 8][wn] = qB;
        }
    }
    __syncthreads();

#pragma unroll
    for (int mt = 0; mt < 4; mt++) {
#pragma unroll
        for (int half = 0; half < 2; half++) {
            const int lr = wm * 64 + mt * 16 + half * 8 + gid;
            const float mu   = (rs[lr][0] + rs[lr][1]) * (1.0f / 128.0f);
            const float var  = (rq[lr][0] + rq[lr][1]) * (1.0f / 128.0f) - mu * mu;
            const float rstd = rsqrtf(var + 1e-5f);
            const int seg = (lr >= bndry) ? 1 : 0;
            const int bg  = b0r + seg;
            const int lrw = (m0 + lr) - bg * LP;
            __half* dst = gHn_h + ((size_t)(hh * B_ + bg) * LP + lrw) * DH;
#pragma unroll
            for (int nt = 0; nt < 8; nt++) {
                const float o0 = (acc[mt][nt][half * 2 + 0] - mu) * rstd * gg[nt][0] + bb[nt][0];
                const float o1 = (acc[mt][nt][half * 2 + 1] - mu) * rstd * gg[nt][1] + bb[nt][1];
                __half2 hv;
                hv.x = __float2half_rn(o0);
                hv.y = __float2half_rn(o1);
                *(__half2*)(dst + wn * 64 + nt * 8 + 2 * tig) = hv;
            }
        }
    }
}

// =====================================================================
// K2: cov via fp16 mma single-pass; column sums + tile means computed
// IN-KERNEL from the smem tiles; rank-1 centering; L2 norm.  <- probe
// =====================================================================
#define CRS2   136
#define CRSB2  (CRS2 * 2)               // 272 B
#define CTILE2 (208 * CRSB2)            // 56576
#define COV_SMEM (2 * CTILE2)           // 113,152

__global__ void __launch_bounds__(256) k_cov_mma()
{
    extern __shared__ char csm[];
    const uint32_t sb = smem_u32(csm);
    __shared__ float colsq[DH];
    __shared__ float s1s[DH];
    __shared__ float s2s[DH];
    __shared__ float sm12[2];

    const int p = blockIdx.x;
    const int b = blockIdx.y;
    const int tid  = threadIdx.x;
    const int wid  = tid >> 5;
    const int lane = tid & 31;
    const int wm = wid >> 1;
    const int wn = wid & 1;

    const __half* Asrc = gHn_h + ((size_t)(p * B_ + b)) * LP * DH;
    const __half* Bhs  = gHn_h + ((size_t)((p + 1) * B_ + b)) * LP * DH;

    const uint32_t tA = sb, tBh = sb + CTILE2;

    for (int i = tid; i < 2 * 12 * 17; i += 256) {
        const int tile = i / 204;
        const int rem  = i % 204;
        const int r    = rem / 17;
        const int c    = rem % 17;
        *(uint4*)(csm + (size_t)tile * CTILE2 + (196 + r) * CRSB2 + c * 16) =
            make_uint4(0u, 0u, 0u, 0u);
    }
    for (int t = tid; t < LP * 16; t += 256) {
        const int row = t >> 4;
        const int ch  = t & 15;
        const uint32_t doff = (uint32_t)row * CRSB2 + ch * 16;
        const size_t   goff = (size_t)row * DH + ch * 8;
        cp16(tA  + doff, Asrc + goff);
        cp16(tBh + doff, Bhs + goff);
    }
    CP_COMMIT();
    if (tid < DH) colsq[tid] = 0.f;
    CP_WAIT0();
    __syncthreads();

    // ---- column sums from smem tiles (tid<128: tile A, else tile B) ----
    {
        const int col = tid & 127;
        const __half* tp = (const __half*)(csm + ((tid < 128) ? 0 : CTILE2)) + col;
        float s = 0.f;
#pragma unroll 4
        for (int r = 0; r < LP; r++) s += __half2float(tp[r * CRS2]);
        if (tid < 128) s1s[col] = s; else s2s[col] = s;
    }
    __syncthreads();
    if (tid < 64) {
        float* src = (tid < 32) ? s1s : s2s;
        const int l = tid & 31;
        float t = src[l] + src[l + 32] + src[l + 64] + src[l + 96];
#pragma unroll
        for (int o = 16; o; o >>= 1) t += __shfl_xor_sync(0xffffffffu, t, o);
        if (l == 0) sm12[tid >> 5] = t * (1.0f / (LP * DH));
    }
    __syncthreads();

    const uint32_t ar = (lane & 7) + ((lane >> 4) << 3);
    const uint32_t ac = ((lane >> 3) & 1) * 16;
    const uint32_t br = (lane & 7) + (((lane >> 3) & 1) << 3);
    const uint32_t bc = (uint32_t)(lane >> 4) * 16;

    uint32_t a_off[2], b_off[4];
#pragma unroll
    for (int mt = 0; mt < 2; mt++)
        a_off[mt] = ar * CRSB2 + (uint32_t)(wm * 32 + mt * 16) * 2 + ac;
#pragma unroll
    for (int g = 0; g < 4; g++)
        b_off[g] = br * CRSB2 + (uint32_t)(wn * 64 + g * 16) * 2 + bc;

    float acc[2][8][4];
#pragma unroll
    for (int mt = 0; mt < 2; mt++)
#pragma unroll
        for (int nt = 0; nt < 8; nt++)
#pragma unroll
            for (int e = 0; e < 4; e++) acc[mt][nt][e] = 0.f;

#pragma unroll
    for (int ks = 0; ks < 13; ks++) {
        const uint32_t kb = (uint32_t)ks * 16 * CRSB2;
        uint32_t ah[2][4];
#pragma unroll
        for (int mt = 0; mt < 2; mt++)
            ldx4t(ah[mt], tA + a_off[mt] + kb);
#pragma unroll
        for (int g = 0; g < 4; g++) {
            uint32_t bh[4];
            ldx4t(bh, tBh + b_off[g] + kb);
#pragma unroll
            for (int mt = 0; mt < 2; mt++) {
                mma16816(acc[mt][2 * g],     ah[mt], bh[0], bh[1]);
                mma16816(acc[mt][2 * g + 1], ah[mt], bh[2], bh[3]);
            }
        }
    }

    const float m1 = sm12[0];
    const float m2 = sm12[1];
    const float c12 = (float)LP * m1 * m2;
    const int gid = lane >> 2;
    const int tig = lane & 3;
#pragma unroll
    for (int mt = 0; mt < 2; mt++) {
        const int d0 = wm * 32 + mt * 16 + gid;
        const float t1a = m2 * s1s[d0]     - c12;
        const float t1b = m2 * s1s[d0 + 8] - c12;
#pragma unroll
        for (int nt = 0; nt < 8; nt++) {
            const int e0 = wn * 64 + nt * 8 + 2 * tig;
            const float t2a = m1 * s2s[e0];
            const float t2b = m1 * s2s[e0 + 1];
            acc[mt][nt][0] -= t1a + t2a;
            acc[mt][nt][1] -= t1a + t2b;
            acc[mt][nt][2] -= t1b + t2a;
            acc[mt][nt][3] -= t1b + t2b;
        }
    }

#pragma unroll
    for (int nt = 0; nt < 8; nt++) {
        float s0 = acc[0][nt][0] * acc[0][nt][0] + acc[0][nt][2] * acc[0][nt][2]
                 + acc[1][nt][0] * acc[1][nt][0] + acc[1][nt][2] * acc[1][nt][2];
        float s1 = acc[0][nt][1] * acc[0][nt][1] + acc[0][nt][3] * acc[0][nt][3]
                 + acc[1][nt][1] * acc[1][nt][1] + acc[1][nt][3] * acc[1][nt][3];
#pragma unroll
        for (int o = 4; o <= 16; o <<= 1) {
            s0 += __shfl_xor_sync(0xffffffffu, s0, o);
            s1 += __shfl_xor_sync(0xffffffffu, s1, o);
        }
        if (lane < 4) {
            const int col = wn * 64 + nt * 8 + 2 * lane;
            atomicAdd(&colsq[col], s0);
            atomicAdd(&colsq[col + 1], s1);
        }
    }
    __syncthreads();

    float* outb = g_cov + ((size_t)(b * 3 + p)) * (DH * DH);
#pragma unroll
    for (int nt = 0; nt < 8; nt++) {
        const int col = wn * 64 + nt * 8 + 2 * tig;
        const float i0 = 1.0f / fmaxf(sqrtf(colsq[col]),     (float)LP * 1e-12f);
        const float i1 = 1.0f / fmaxf(sqrtf(colsq[col + 1]), (float)LP * 1e-12f);
#pragma unroll
        for (int mt = 0; mt < 2; mt++) {
            const int r0 = wm * 32 + mt * 16 + gid;
            float2 v0 = make_float2(acc[mt][nt][0] * i0, acc[mt][nt][1] * i1);
            float2 v1 = make_float2(acc[mt][nt][2] * i0, acc[mt][nt][3] * i1);
            *(float2*)(outb + (size_t)r0 * DH + col)       = v0;
            *(float2*)(outb + (size_t)(r0 + 8) * DH + col) = v1;
        }
    }
}

// =====================================================================
// K3: fused conv1 -> GELU -> conv2 ; emits flat as fp16 hi/lo (padded)
// =====================================================================
#define CONV_CS_B  (3 * 66 * 128 * 4)
#define CONV_SMEM  (CONV_CS_B + 3 * 3969 * 4)  // 149,004

__global__ void __launch_bounds__(256) k_conv(
    const float* __restrict__ w1, const float* __restrict__ w2)
{
    extern __shared__ char cvsm[];
    float* cs = (float*)cvsm;
    float* z1 = (float*)(cvsm + CONV_CS_B);
    __shared__ float w1s[81];
    __shared__ float w2s[81];

    const int b = blockIdx.x;
    const int tid = threadIdx.x;
    if (tid < 81) { w1s[tid] = w1[tid]; w2s[tid] = w2[tid]; }

    const float* cb = g_cov + (size_t)b * 3 * DH * DH;

#pragma unroll 1
    for (int ph = 0; ph < 2; ph++) {
        const int r0 = ph * 64;
        const int nr = ph ? 64 : 66;
        const int y0 = ph ? 32 : 0;
        const int ny = ph ? 31 : 32;
        __syncthreads();
        for (int i = tid; i < 3 * nr * 32; i += 256) {
            const int c  = i / (nr * 32);
            const int rr = (i / 32) % nr;
            const int q  = i % 32;
            *(float4*)(cs + (c * 66 + rr) * 128 + q * 4) =
                *(const float4*)(cb + (size_t)c * (DH * DH) + (r0 + rr) * DH + q * 4);
        }
        __syncthreads();
        for (int idx = tid; idx < 3 * ny * 63; idx += 256) {
            const int c = idx / (ny * 63);
            const int r = idx % (ny * 63);
            const int y = y0 + r / 63;
            const int x = r % 63;
            float s = 0.f;
#pragma unroll
            for (int ci = 0; ci < 3; ci++)
#pragma unroll
                for (int ky = 0; ky < 3; ky++)
#pragma unroll
                    for (int kx = 0; kx < 3; kx++)
                        s += cs[(ci * 66 + (2 * y + ky - r0)) * 128 + 2 * x + kx]
                           * w1s[((c * 3 + ci) * 3 + ky) * 3 + kx];
            s = 0.5f * s * (1.0f + erff(s * 0.70710678118654752f));
            z1[c * 3969 + y * 63 + x] = s;
        }
    }
    __syncthreads();

    __half* fh = gF_h + (size_t)b * FPAD;
    __half* fl = gF_l + (size_t)b * FPAD;
    for (int idx = tid; idx < FLATN; idx += 256) {
        const int c = idx / 961;
        const int r = idx % 961;
        const int y = r / 31, x = r % 31;
        float s = 0.f;
#pragma unroll
        for (int ci = 0; ci < 3; ci++)
#pragma unroll
            for (int ky = 0; ky < 3; ky++)
#pragma unroll
                for (int kx = 0; kx < 3; kx++)
                    s += z1[ci * 3969 + (2 * y + ky) * 63 + (2 * x + kx)]
                       * w2s[((c * 3 + ci) * 3 + ky) * 3 + kx];
        const __half hv = __float2half_rn(s);
        fh[idx] = hv;
        fl[idx] = __float2half_rn(s - __half2float(hv));
    }
    for (int idx = FLATN + tid; idx < FPAD; idx += 256) {
        fh[idx] = __float2half_rn(0.f);
        fl[idx] = __float2half_rn(0.f);
    }
}

// =====================================================================
// K4: classifier head via fp16 mma, 3-pass split, k-split=4 + atomicAdd
// =====================================================================
#define HRSB   80
#define HBRS   272
#define OFF_AH2 0
#define OFF_AL2 (64 * HRSB)
#define OFF_BH2 (2 * 64 * HRSB)
#define OFF_BL2 (OFF_BH2 + 32 * HBRS)
#define HSTAGE  (OFF_BL2 + 32 * HBRS)   // 27648
#define HEAD_SMEM (2 * HSTAGE)          // 55296

__device__ __forceinline__ void head_load_stage(
    uint32_t sb, int buf, int chunk, int m0, int n0, int tid)
{
    const uint32_t stg = sb + buf * HSTAGE;
    const bool in_cls = (chunk < HK_CLS_CHUNKS);
    const int  kr     = in_cls ? chunk * 32 : (chunk - HK_CLS_CHUNKS) * 32;
    const __half* Ah = in_cls ? gCls_h : gF_h;
    const __half* Al = in_cls ? gCls_l : gF_l;
    const __half* Bh = in_cls ? gW1_h  : gW2_h;
    const __half* Bl = in_cls ? gW1_l  : gW2_l;
    const int astr = in_cls ? D_ : FPAD;

    {
        const int idx = tid;
        const int row = idx >> 2;
        const int q   = idx & 3;
        const uint32_t doff = (uint32_t)row * HRSB + q * 16;
        const size_t goff = (size_t)(m0 + row) * astr + kr + q * 8;
        cp16(stg + OFF_AH2 + doff, Ah + goff);
        cp16(stg + OFF_AL2 + doff, Al + goff);
    }
#pragma unroll
    for (int j = 0; j < 2; j++) {
        const int idx = j * 256 + tid;
        const int row = idx >> 4;
        const int q   = idx & 15;
        const uint32_t doff = (uint32_t)row * HBRS + q * 16;
        const size_t goff = (size_t)(kr + row) * NPAD + n0 + q * 8;
        cp16(stg + OFF_BH2 + doff, Bh + goff);
        cp16(stg + OFF_BL2 + doff, Bl + goff);
    }
}

__global__ void __launch_bounds__(256) k_head_mma(float* __restrict__ out)
{
    extern __shared__ char hsm[];
    const uint32_t sb = smem_u32(hsm);
    const int tid  = threadIdx.x;
    const int wid  = tid >> 5;
    const int lane = tid & 31;
    const int wm = wid >> 2;
    const int wn = wid & 3;
    const int m0 = blockIdx.x * 64;
    const int n0 = blockIdx.y * 128;
    const int c0 = blockIdx.z * HK_SPLIT;

    const uint32_t a_row = (lane & 15);
    const uint32_t a_col = (uint32_t)(lane >> 4) * 16;
    const uint32_t br = (lane & 7) + (((lane >> 3) & 1) << 3);
    const uint32_t bc = (uint32_t)(lane >> 4) * 16;

    uint32_t a_off[2], b_off[2];
#pragma unroll
    for (int mt = 0; mt < 2; mt++)
        a_off[mt] = (uint32_t)(wm * 32 + mt * 16 + a_row) * HRSB + a_col;
#pragma unroll
    for (int g = 0; g < 2; g++)
        b_off[g] = br * HBRS + (uint32_t)(wn * 32 + g * 16) * 2 + bc;

    float acc[2][4][4];
#pragma unroll
    for (int mt = 0; mt < 2; mt++)
#pragma unroll
        for (int nf = 0; nf < 4; nf++)
#pragma unroll
            for (int e = 0; e < 4; e++) acc[mt][nf][e] = 0.f;

    head_load_stage(sb, 0, c0, m0, n0, tid);
    CP_COMMIT();

    for (int i = 0; i < HK_SPLIT; i++) {
        if (i + 1 < HK_SPLIT) {
            head_load_stage(sb, (i + 1) & 1, c0 + i + 1, m0, n0, tid);
            CP_COMMIT();
            CP_WAIT1();
        } else {
            CP_WAIT0();
        }
        __syncthreads();

        const uint32_t stg = sb + (i & 1) * HSTAGE;
#pragma unroll
        for (int ks = 0; ks < 2; ks++) {
            uint32_t ah[2][4], al[2][4];
#pragma unroll
            for (int mt = 0; mt < 2; mt++) {
                ldx4(ah[mt], stg + OFF_AH2 + a_off[mt] + ks * 32);
                ldx4(al[mt], stg + OFF_AL2 + a_off[mt] + ks * 32);
            }
            const uint32_t kbb = (uint32_t)ks * 16 * HBRS;
#pragma unroll
            for (int g = 0; g < 2; g++) {
                uint32_t bh[4], bl[4];
                ldx4t(bh, stg + OFF_BH2 + b_off[g] + kbb);
                ldx4t(bl, stg + OFF_BL2 + b_off[g] + kbb);
#pragma unroll
                for (int mt = 0; mt < 2; mt++) {
                    mma16816(acc[mt][2 * g],     ah[mt], bh[0], bh[1]);
                    mma16816(acc[mt][2 * g],     ah[mt], bl[0], bl[1]);
                    mma16816(acc[mt][2 * g],     al[mt], bh[0], bh[1]);
                    mma16816(acc[mt][2 * g + 1], ah[mt], bh[2], bh[3]);
                    mma16816(acc[mt][2 * g + 1], ah[mt], bl[2], bl[3]);
                    mma16816(acc[mt][2 * g + 1], al[mt], bh[2], bh[3]);
                }
            }
        }
        __syncthreads();
    }

    const int gid = lane >> 2;
    const int tig = lane & 3;
#pragma unroll
    for (int mt = 0; mt < 2; mt++) {
        const int r0 = m0 + wm * 32 + mt * 16 + gid;
#pragma unroll
        for (int nf = 0; nf < 4; nf++) {
            const int col = n0 + wn * 32 + nf * 8 + 2 * tig;
            if (col < NC) {
                atomicAdd(out + (size_t)r0 * NC + col,       0.5f * acc[mt][nf][0]);
                atomicAdd(out + (size_t)r0 * NC + col + 1,   0.5f * acc[mt][nf][1]);
                atomicAdd(out + (size_t)(r0 + 8) * NC + col,     0.5f * acc[mt][nf][2]);
                atomicAdd(out + (size_t)(r0 + 8) * NC + col + 1, 0.5f * acc[mt][nf][3]);
            }
        }
    }
}

// =====================================================================
// launch
// =====================================================================
extern "C" void kernel_launch(void* const* d_in, const int* in_sizes, int n_in,
                              void* d_out, int out_size)
{
    const float* cls_token = (const float*)d_in[0];
    const float* x         = (const float*)d_in[1];
    const float* proj_w    = (const float*)d_in[2];
    const float* proj_b    = (const float*)d_in[3];
    const float* ln_g      = (const float*)d_in[4];
    const float* ln_b      = (const float*)d_in[5];
    const float* conv1_w   = (const float*)d_in[6];
    const float* conv2_w   = (const float*)d_in[7];
    const float* cls1_w    = (const float*)d_in[8];
    const float* cls1_b    = (const float*)d_in[9];
    const float* cls2_w    = (const float*)d_in[10];
    const float* cls2_b    = (const float*)d_in[11];
    float* out = (float*)d_out;

    cudaFuncSetAttribute(k_gemm_mma,
                         cudaFuncAttributeMaxDynamicSharedMemorySize, GEMM_SMEM);
    cudaFuncSetAttribute(k_cov_mma,
                         cudaFuncAttributeMaxDynamicSharedMemorySize, COV_SMEM);
    cudaFuncSetAttribute(k_conv,
                         cudaFuncAttributeMaxDynamicSharedMemorySize, CONV_SMEM);
    cudaFuncSetAttribute(k_head_mma,
                         cudaFuncAttributeMaxDynamicSharedMemorySize, HEAD_SMEM);

    k_convA<<<2048, 256>>>(x);                                        // 0
    k_convW<<<dim3(HD / 32, D_ / 32), 256>>>(proj_w);                 // 1
    k_gemm_mma<<<dim3(392, 4), 128, GEMM_SMEM>>>(proj_b, ln_g, ln_b); // 2
    k_cov_mma<<<dim3(3, B_), 256, COV_SMEM>>>();                      // 3 <- ncu probe
    k_convH<<<2048, 256>>>(cls1_w, cls2_w, cls_token,
                           cls1_b, cls2_b, out);                      // 4
    k_conv<<<B_, 256, CONV_SMEM>>>(conv1_w, conv2_w);                 // 5
    k_head_mma<<<dim3(4, 8, 4), 256, HEAD_SMEM>>>(out);               // 6
}